// round 9
// baseline (speedup 1.0000x reference)
#include <cuda_runtime.h>
#include <cuda_bf16.h>
#include <math.h>
#include <stdint.h>

#define BATCH 8
#define SEQ 512
#define DIM 768
#define NHEAD 12
#define DH 64
#define INNER 768
#define MLPDIM 3072
#define DEPTH 4
#define ROWS (BATCH * SEQ)
#define LSCALE 0.1f
#define EPS 1e-5f
#define ATT_SCALE 0.125f
#define SSQ (SEQ * SEQ)

typedef __nv_bfloat16 bf16;

// ---------------- scratch (device globals) ----------------
__device__ bf16 g_h_hi [ROWS * DIM],    g_h_lo [ROWS * DIM];
__device__ bf16 g_q_hi [ROWS * INNER],  g_q_lo [ROWS * INNER];
__device__ bf16 g_k_hi [ROWS * INNER];
__device__ bf16 g_vT_hi[ROWS * INNER];
__device__ float g_dots[BATCH * NHEAD * SSQ];
__device__ bf16 g_at_hi[BATCH * NHEAD * SSQ], g_at_lo[BATCH * NHEAD * SSQ];
__device__ bf16 g_o_hi [ROWS * INNER],  g_o_lo [ROWS * INNER];
__device__ bf16 g_m_hi [ROWS * MLPDIM], g_m_lo [ROWS * MLPDIM];
// transposed weights (hi only — B operand is single bf16 now)
__device__ bf16 g_wqT_hi[DEPTH * DIM * INNER];
__device__ bf16 g_wkT_hi[DEPTH * DIM * INNER];
__device__ bf16 g_wvT_hi[DEPTH * DIM * INNER];
__device__ bf16 g_woT_hi[DEPTH * INNER * DIM];
__device__ bf16 g_w1T_hi[DEPTH * DIM * MLPDIM];
__device__ bf16 g_w2T_hi[DEPTH * MLPDIM * DIM];

__device__ __forceinline__ float gelu_tanh(float x) {
    float x3 = x * x * x;
    return 0.5f * x * (1.0f + tanhf(0.7978845608028654f * (x + 0.044715f * x3)));
}
__device__ __forceinline__ void split2(float v, bf16& h, bf16& l) {
    h = __float2bfloat16(v);
    l = __float2bfloat16(v - __bfloat162float(h));
}

__device__ __forceinline__ void cp16(unsigned s, const void* g) {
    asm volatile("cp.async.cg.shared.global [%0], [%1], 16;\n" :: "r"(s), "l"(g));
}
__device__ __forceinline__ void cp_commit() {
    asm volatile("cp.async.commit_group;\n");
}
template<int N> __device__ __forceinline__ void cp_wait() {
    asm volatile("cp.async.wait_group %0;\n" :: "n"(N));
}
__device__ __forceinline__ void ldsm4(unsigned& r0, unsigned& r1, unsigned& r2,
                                      unsigned& r3, unsigned addr) {
    asm volatile("ldmatrix.sync.aligned.m8n8.x4.shared.b16 {%0,%1,%2,%3}, [%4];\n"
                 : "=r"(r0), "=r"(r1), "=r"(r2), "=r"(r3) : "r"(addr));
}
#define MMA16(d, a, b0, b1) \
    asm volatile("mma.sync.aligned.m16n8k16.row.col.f32.bf16.bf16.f32 " \
                 "{%0,%1,%2,%3},{%4,%5,%6,%7},{%8,%9},{%0,%1,%2,%3};\n" \
                 : "+f"(d[0]), "+f"(d[1]), "+f"(d[2]), "+f"(d[3])       \
                 : "r"(a[0]), "r"(a[1]), "r"(a[2]), "r"(a[3]), "r"(b0), "r"(b1))

// ---------------- transpose weights -> bf16 hi only ----------------
__global__ __launch_bounds__(256) void wsplit_t(const float* __restrict__ in, int ldin,
                                                int K, int N, bf16* __restrict__ oh) {
    __shared__ float t[32][33];
    int tx = threadIdx.x, ty = threadIdx.y;
    int k0 = blockIdx.x * 32, n0 = blockIdx.y * 32;
    #pragma unroll
    for (int r = ty; r < 32; r += 8)
        t[r][tx] = in[(size_t)(k0 + r) * ldin + n0 + tx];
    __syncthreads();
    #pragma unroll
    for (int r = ty; r < 32; r += 8) {
        int n = n0 + r, k = k0 + tx;
        oh[(size_t)n * K + k] = __float2bfloat16(t[tx][r]);
    }
}

// ---------------- LayerNorm -> split ----------------
__global__ __launch_bounds__(256) void ln_split(const float* __restrict__ x,
                                                const float* __restrict__ scale,
                                                bf16* __restrict__ oh, bf16* __restrict__ ol) {
    int row = blockIdx.x;
    const float* xr = x + (size_t)row * DIM;
    int tid = threadIdx.x;
    float s = 0.f, s2 = 0.f;
    for (int c = tid; c < DIM; c += 256) { float v = xr[c]; s += v; s2 += v * v; }
    __shared__ float rs[256], rs2[256];
    rs[tid] = s; rs2[tid] = s2;
    __syncthreads();
    for (int off = 128; off > 0; off >>= 1) {
        if (tid < off) { rs[tid] += rs[tid + off]; rs2[tid] += rs2[tid + off]; }
        __syncthreads();
    }
    float mu = rs[0] * (1.0f / DIM);
    float var = rs2[0] * (1.0f / DIM) - mu * mu;
    float rstd = rsqrtf(var + EPS);
    for (int c = tid; c < DIM; c += 256) {
        float v = (xr[c] - mu) * rstd * scale[c];
        bf16 h, l; split2(v, h, l);
        size_t idx = (size_t)row * DIM + c;
        oh[idx] = h; ol[idx] = l;
    }
}

// ---------------- fused mix_pre -> softmax -> mix_post -> split ----------------
__global__ __launch_bounds__(384) void attn_mix_softmax(
    const float* __restrict__ dots, const float* __restrict__ mp,
    const float* __restrict__ mq, bf16* __restrict__ ah, bf16* __restrict__ al)
{
    __shared__ float S[NHEAD][SEQ];
    __shared__ float T[NHEAD][SEQ];
    int tid = threadIdx.x, lane = tid & 31, g = tid >> 5;
    int b = blockIdx.x >> 9, i = blockIdx.x & 511;
    const float* base = dots + ((size_t)(b * NHEAD) * SEQ + i) * SEQ;

    #pragma unroll
    for (int it = 0; it < 4; it++) {
        int idx = tid + it * 384;
        int h = idx >> 7, jq = (idx & 127) << 2;
        *(float4*)&S[h][jq] = *(const float4*)(base + (size_t)h * SSQ + jq);
    }
    __syncthreads();

    float mcol[NHEAD];
    #pragma unroll
    for (int h = 0; h < NHEAD; h++) mcol[h] = __ldg(&mp[h * NHEAD + g]);
    float v[16];
    float mx = -1e30f;
    #pragma unroll
    for (int k = 0; k < 16; k++) {
        int j = lane + k * 32;
        float a = 0.f;
        #pragma unroll
        for (int h = 0; h < NHEAD; h++) a += S[h][j] * mcol[h];
        v[k] = a; mx = fmaxf(mx, a);
    }
    #pragma unroll
    for (int off = 16; off > 0; off >>= 1)
        mx = fmaxf(mx, __shfl_xor_sync(0xffffffffu, mx, off));
    float s = 0.f;
    #pragma unroll
    for (int k = 0; k < 16; k++) { v[k] = __expf(v[k] - mx); s += v[k]; }
    #pragma unroll
    for (int off = 16; off > 0; off >>= 1)
        s += __shfl_xor_sync(0xffffffffu, s, off);
    float inv = 1.0f / s;
    #pragma unroll
    for (int k = 0; k < 16; k++) T[g][lane + k * 32] = v[k] * inv;
    __syncthreads();

    float qcol[NHEAD];
    #pragma unroll
    for (int h = 0; h < NHEAD; h++) qcol[h] = __ldg(&mq[h * NHEAD + g]);
    size_t ob = ((size_t)((b * NHEAD + g) * SEQ) + i) * SEQ;
    #pragma unroll
    for (int k = 0; k < 16; k++) {
        int j = lane + k * 32;
        float a = 0.f;
        #pragma unroll
        for (int h = 0; h < NHEAD; h++) a += T[h][j] * qcol[h];
        bf16 hh, ll; split2(a, hh, ll);
        ah[ob + j] = hh; al[ob + j] = ll;
    }
}

// ---------------- bf16 2-term split GEMM, BK=64, 3-stage cp.async ----------
// A[m][k] split hi/lo (exact), B[n][k] single bf16 (rounded). acc f32.
// epi: 0 f32 store*alpha   1 split-store    2 X += (v+bias)*LS
//      3 vT scatter (hi)   4 gelu split     5 hi-only store
template<int BN, int WARPS_M, int WARPS_N>
__global__ __launch_bounds__(256) void tgemm2(
    const bf16* __restrict__ Ahp, const bf16* __restrict__ Alp, int lda, long sAb, long sAh,
    const bf16* __restrict__ Bhp, int ldb, long sBb, long sBh,
    float* __restrict__ Cf, bf16* __restrict__ Chi, bf16* __restrict__ Clo,
    int ldc, long sCb, long sCh, const float* __restrict__ bias,
    int K, int nH, float alpha, int epi)
{
    constexpr int BM = 128, BK = 64, STAGES = 3;
    constexpr int RB = 144;                       // 128B data + 16B pad per row
    constexpr unsigned OFF_AL = BM * RB;
    constexpr unsigned OFF_B  = 2u * BM * RB;
    constexpr unsigned STAGE  = (2 * BM + BN) * RB;
    constexpr int WM = BM / WARPS_M, WN = BN / WARPS_N;
    constexpr int MF = WM / 16, NF = WN / 8, NF2 = NF / 2;

    extern __shared__ __align__(16) char ds[];
    unsigned sb0 = (unsigned)__cvta_generic_to_shared(ds);

    int tid = threadIdx.x, lane = tid & 31, warp = tid >> 5;
    int wm = warp / WARPS_N, wn = warp % WARPS_N;
    int bz = blockIdx.z / nH, hz = blockIdx.z % nH;
    int row0 = blockIdx.y * BM, n0 = blockIdx.x * BN;

    const bf16* Ah = Ahp + (size_t)bz * sAb + (size_t)hz * sAh + (size_t)row0 * lda;
    const bf16* Al = Alp + (size_t)bz * sAb + (size_t)hz * sAh + (size_t)row0 * lda;
    const bf16* Bh = Bhp + (size_t)bz * sBb + (size_t)hz * sBh + (size_t)n0 * ldb;

    const int KT = K / BK;
    constexpr int TOT = (2 * BM + BN) * 8;        // 16B chunks per stage

    auto load_stage = [&](int t) {
        unsigned sbm = sb0 + (unsigned)(t % STAGES) * STAGE;
        int k0 = t * BK;
        #pragma unroll
        for (int c = tid; c < TOT; c += 256) {
            int cc = c; const bf16* g; unsigned reg; int ld;
            if (cc < BM * 8)          { g = Ah; reg = 0;      ld = lda; }
            else if (cc < 2 * BM * 8) { cc -= BM * 8; g = Al; reg = OFF_AL; ld = lda; }
            else                      { cc -= 2 * BM * 8; g = Bh; reg = OFF_B; ld = ldb; }
            int r = cc >> 3, q = cc & 7;
            cp16(sbm + reg + (unsigned)(r * RB + q * 16),
                 g + (size_t)r * ld + k0 + q * 8);
        }
    };

    float acc[MF][NF][4] = {};

    #pragma unroll
    for (int s = 0; s < STAGES - 1; s++)
        if (s < KT) { load_stage(s); cp_commit(); }

    int arow = lane & 15;
    int acol = (lane >> 4) << 4;
    int nrow = (lane & 7) | ((lane & 16) >> 1);
    int ncol = (lane & 8) ? 16 : 0;

    for (int t = 0; t < KT; t++) {
        if (t + 1 < KT) cp_wait<1>(); else cp_wait<0>();
        __syncthreads();
        if (t + STAGES - 1 < KT) { load_stage(t + STAGES - 1); cp_commit(); }

        unsigned sbm = sb0 + (unsigned)(t % STAGES) * STAGE;
        #pragma unroll
        for (int kk = 0; kk < BK / 16; kk++) {
            unsigned ah[MF][4], al[MF][4], bh[NF2][4];
            #pragma unroll
            for (int mi = 0; mi < MF; mi++) {
                unsigned base = sbm + (unsigned)((wm * WM + mi * 16 + arow) * RB + kk * 32 + acol);
                ldsm4(ah[mi][0], ah[mi][1], ah[mi][2], ah[mi][3], base);
                ldsm4(al[mi][0], al[mi][1], al[mi][2], al[mi][3], base + OFF_AL);
            }
            #pragma unroll
            for (int j = 0; j < NF2; j++) {
                unsigned base = sbm + OFF_B + (unsigned)((wn * WN + j * 16 + nrow) * RB + kk * 32 + ncol);
                ldsm4(bh[j][0], bh[j][1], bh[j][2], bh[j][3], base);
            }
            #pragma unroll
            for (int mi = 0; mi < MF; mi++)
                #pragma unroll
                for (int ni = 0; ni < NF; ni++) {
                    int j = ni >> 1, o = (ni & 1) * 2;
                    MMA16(acc[mi][ni], ah[mi], bh[j][o], bh[j][o + 1]);
                    MMA16(acc[mi][ni], al[mi], bh[j][o], bh[j][o + 1]);
                }
        }
    }

    // ---- epilogue ----
    float* Cfb = Cf ? Cf + (size_t)bz * sCb + (size_t)hz * sCh : nullptr;
    bf16* Chb = Chi ? Chi + (size_t)bz * sCb + (size_t)hz * sCh : nullptr;
    bf16* Clb = Clo ? Clo + (size_t)bz * sCb + (size_t)hz * sCh : nullptr;

    #pragma unroll
    for (int mi = 0; mi < MF; mi++) {
        #pragma unroll
        for (int ni = 0; ni < NF; ni++) {
            int r0 = row0 + wm * WM + mi * 16 + (lane >> 2);
            int cn = n0 + wn * WN + ni * 8 + 2 * (lane & 3);
            #pragma unroll
            for (int half = 0; half < 2; half++) {
                int r = r0 + half * 8;
                float v0 = acc[mi][ni][half * 2 + 0] * alpha;
                float v1 = acc[mi][ni][half * 2 + 1] * alpha;
                if (epi == 0) {
                    *(float2*)(Cfb + (size_t)r * ldc + cn) = make_float2(v0, v1);
                } else if (epi == 1) {
                    size_t off = (size_t)r * ldc + cn;
                    bf16 h0, l0, h1, l1; split2(v0, h0, l0); split2(v1, h1, l1);
                    __nv_bfloat162 ph; ph.x = h0; ph.y = h1;
                    __nv_bfloat162 pl; pl.x = l0; pl.y = l1;
                    *(__nv_bfloat162*)(Chb + off) = ph;
                    *(__nv_bfloat162*)(Clb + off) = pl;
                } else if (epi == 2) {
                    size_t off = (size_t)r * ldc + cn;
                    float2 old = *(float2*)(Cfb + off);
                    old.x += (v0 + bias[cn]) * LSCALE;
                    old.y += (v1 + bias[cn + 1]) * LSCALE;
                    *(float2*)(Cfb + off) = old;
                } else if (epi == 3) {
                    int bb = r >> 9, ii = r & 511;
                    size_t idx = ((size_t)bb * INNER + cn) * SEQ + ii;
                    Chb[idx] = __float2bfloat16(v0);
                    Chb[idx + SEQ] = __float2bfloat16(v1);
                } else if (epi == 4) {
                    size_t off = (size_t)r * ldc + cn;
                    float t0 = gelu_tanh(v0 + bias[cn]);
                    float t1 = gelu_tanh(v1 + bias[cn + 1]);
                    bf16 h0, l0, h1, l1; split2(t0, h0, l0); split2(t1, h1, l1);
                    __nv_bfloat162 ph; ph.x = h0; ph.y = h1;
                    __nv_bfloat162 pl; pl.x = l0; pl.y = l1;
                    *(__nv_bfloat162*)(Chb + off) = ph;
                    *(__nv_bfloat162*)(Clb + off) = pl;
                } else {   // 5: hi-only store
                    size_t off = (size_t)r * ldc + cn;
                    __nv_bfloat162 ph;
                    ph.x = __float2bfloat16(v0); ph.y = __float2bfloat16(v1);
                    *(__nv_bfloat162*)(Chb + off) = ph;
                }
            }
        }
    }
}

// ---------------- launch ----------------
extern "C" void kernel_launch(void* const* d_in, const int* in_sizes, int n_in,
                              void* d_out, int out_size) {
    const float* x_in     = (const float*)d_in[0];
    const float* ln1      = (const float*)d_in[1];
    const float* Wq       = (const float*)d_in[2];
    const float* Wkv      = (const float*)d_in[3];
    const float* mix_pre  = (const float*)d_in[4];
    const float* mix_post = (const float*)d_in[5];
    const float* Wo       = (const float*)d_in[6];
    const float* bo       = (const float*)d_in[7];
    const float* ln2      = (const float*)d_in[8];
    const float* W1       = (const float*)d_in[9];
    const float* b1       = (const float*)d_in[10];
    const float* W2       = (const float*)d_in[11];
    const float* b2       = (const float*)d_in[12];

    float* X = (float*)d_out;

    bf16 *h_hi, *h_lo, *q_hi, *q_lo, *k_hi, *vT_hi;
    bf16 *at_hi, *at_lo, *o_hi, *o_lo, *m_hi, *m_lo;
    bf16 *wqT, *wkT, *wvT, *woT, *w1T, *w2T;
    float* dots;
    cudaGetSymbolAddress((void**)&h_hi, g_h_hi);   cudaGetSymbolAddress((void**)&h_lo, g_h_lo);
    cudaGetSymbolAddress((void**)&q_hi, g_q_hi);   cudaGetSymbolAddress((void**)&q_lo, g_q_lo);
    cudaGetSymbolAddress((void**)&k_hi, g_k_hi);
    cudaGetSymbolAddress((void**)&vT_hi, g_vT_hi);
    cudaGetSymbolAddress((void**)&at_hi, g_at_hi); cudaGetSymbolAddress((void**)&at_lo, g_at_lo);
    cudaGetSymbolAddress((void**)&o_hi, g_o_hi);   cudaGetSymbolAddress((void**)&o_lo, g_o_lo);
    cudaGetSymbolAddress((void**)&m_hi, g_m_hi);   cudaGetSymbolAddress((void**)&m_lo, g_m_lo);
    cudaGetSymbolAddress((void**)&wqT, g_wqT_hi);
    cudaGetSymbolAddress((void**)&wkT, g_wkT_hi);
    cudaGetSymbolAddress((void**)&wvT, g_wvT_hi);
    cudaGetSymbolAddress((void**)&woT, g_woT_hi);
    cudaGetSymbolAddress((void**)&w1T, g_w1T_hi);
    cudaGetSymbolAddress((void**)&w2T, g_w2T_hi);
    cudaGetSymbolAddress((void**)&dots, g_dots);

    const int SM128 = 3 * (2 * 128 + 128) * 144;   // 165888
    const int SM64  = 3 * (2 * 128 + 64) * 144;    // 138240
    cudaFuncSetAttribute((const void*)tgemm2<128, 2, 4>,
                         cudaFuncAttributeMaxDynamicSharedMemorySize, SM128);
    cudaFuncSetAttribute((const void*)tgemm2<64, 4, 2>,
                         cudaFuncAttributeMaxDynamicSharedMemorySize, SM64);

    cudaMemcpyAsync(X, x_in, (size_t)ROWS * DIM * sizeof(float),
                    cudaMemcpyDeviceToDevice);

    // ---- weight transpose (hi only) ----
    dim3 tb(32, 8);
    for (int d = 0; d < DEPTH; d++) {
        size_t wo768 = (size_t)d * DIM * INNER;
        size_t w1o = (size_t)d * DIM * MLPDIM;
        wsplit_t<<<dim3(DIM / 32, INNER / 32), tb>>>(Wq + wo768, INNER, DIM, INNER, wqT + wo768);
        wsplit_t<<<dim3(DIM / 32, INNER / 32), tb>>>(Wkv + (size_t)d * DIM * 2 * INNER,
                                                     2 * INNER, DIM, INNER, wkT + wo768);
        wsplit_t<<<dim3(DIM / 32, INNER / 32), tb>>>(Wkv + (size_t)d * DIM * 2 * INNER + INNER,
                                                     2 * INNER, DIM, INNER, wvT + wo768);
        wsplit_t<<<dim3(INNER / 32, DIM / 32), tb>>>(Wo + wo768, DIM, INNER, DIM, woT + wo768);
        wsplit_t<<<dim3(DIM / 32, MLPDIM / 32), tb>>>(W1 + w1o, MLPDIM, DIM, MLPDIM, w1T + w1o);
        wsplit_t<<<dim3(MLPDIM / 32, DIM / 32), tb>>>(W2 + w1o, DIM, MLPDIM, DIM, w2T + w1o);
    }

    for (int d = 0; d < DEPTH; d++) {
        size_t wo768 = (size_t)d * DIM * INNER;
        size_t w1o = (size_t)d * DIM * MLPDIM;

        // ---- attention half ----
        ln_split<<<ROWS, 256>>>(X, ln1 + d * DIM, h_hi, h_lo);

        // q = h @ Wq (split out)
        tgemm2<128, 2, 4><<<dim3(INNER / 128, ROWS / 128, 1), 256, SM128>>>(
            h_hi, h_lo, DIM, 0, 0,
            wqT + wo768, DIM, 0, 0,
            nullptr, q_hi, q_lo, INNER, 0, 0, nullptr,
            DIM, 1, 1.f, 1);
        // k = h @ Wk (hi only)
        tgemm2<128, 2, 4><<<dim3(INNER / 128, ROWS / 128, 1), 256, SM128>>>(
            h_hi, h_lo, DIM, 0, 0,
            wkT + wo768, DIM, 0, 0,
            nullptr, k_hi, nullptr, INNER, 0, 0, nullptr,
            DIM, 1, 1.f, 5);
        // vT = (h @ Wv)^T per head (hi only)
        tgemm2<128, 2, 4><<<dim3(INNER / 128, ROWS / 128, 1), 256, SM128>>>(
            h_hi, h_lo, DIM, 0, 0,
            wvT + wo768, DIM, 0, 0,
            nullptr, vT_hi, nullptr, 0, 0, 0, nullptr,
            DIM, 1, 1.f, 3);

        // dots = scale * q @ k^T per (b,h)
        tgemm2<128, 2, 4><<<dim3(SEQ / 128, SEQ / 128, BATCH * NHEAD), 256, SM128>>>(
            q_hi, q_lo, INNER, (long)SEQ * INNER, DH,
            k_hi, INNER, (long)SEQ * INNER, DH,
            dots, nullptr, nullptr, SEQ, (long)NHEAD * SSQ, (long)SSQ, nullptr,
            DH, NHEAD, ATT_SCALE, 0);

        attn_mix_softmax<<<BATCH * SEQ, 384>>>(dots, mix_pre + d * NHEAD * NHEAD,
                                               mix_post + d * NHEAD * NHEAD, at_hi, at_lo);

        // o = attn @ v (split out)
        tgemm2<64, 4, 2><<<dim3(1, SEQ / 128, BATCH * NHEAD), 256, SM64>>>(
            at_hi, at_lo, SEQ, (long)NHEAD * SSQ, (long)SSQ,
            vT_hi, SEQ, (long)INNER * SEQ, (long)DH * SEQ,
            nullptr, o_hi, o_lo, INNER, (long)SEQ * INNER, DH, nullptr,
            SEQ, NHEAD, 1.f, 1);

        // X += (o @ Wo + bo) * LS
        tgemm2<128, 2, 4><<<dim3(DIM / 128, ROWS / 128, 1), 256, SM128>>>(
            o_hi, o_lo, INNER, 0, 0,
            woT + wo768, INNER, 0, 0,
            X, nullptr, nullptr, DIM, 0, 0, bo + d * DIM,
            INNER, 1, 1.f, 2);

        // ---- MLP half ----
        ln_split<<<ROWS, 256>>>(X, ln2 + d * DIM, h_hi, h_lo);

        tgemm2<128, 2, 4><<<dim3(MLPDIM / 128, ROWS / 128, 1), 256, SM128>>>(
            h_hi, h_lo, DIM, 0, 0,
            w1T + w1o, DIM, 0, 0,
            nullptr, m_hi, m_lo, MLPDIM, 0, 0, b1 + d * MLPDIM,
            DIM, 1, 1.f, 4);

        tgemm2<128, 2, 4><<<dim3(DIM / 128, ROWS / 128, 1), 256, SM128>>>(
            m_hi, m_lo, MLPDIM, 0, 0,
            w2T + w1o, MLPDIM, 0, 0,
            X, nullptr, nullptr, DIM, 0, 0, b2 + d * DIM,
            MLPDIM, 1, 1.f, 2);
    }
}

// round 10
// speedup vs baseline: 1.7072x; 1.7072x over previous
#include <cuda_runtime.h>
#include <cuda_bf16.h>
#include <math.h>
#include <stdint.h>

#define BATCH 8
#define SEQ 512
#define DIM 768
#define NHEAD 12
#define DH 64
#define INNER 768
#define MLPDIM 3072
#define DEPTH 4
#define ROWS (BATCH * SEQ)
#define LSCALE 0.1f
#define EPS 1e-5f
#define ATT_SCALE 0.125f
#define SSQ (SEQ * SEQ)

typedef __nv_bfloat16 bf16;

// ---------------- scratch (device globals) ----------------
__device__ bf16 g_h [ROWS * DIM];
__device__ bf16 g_q [ROWS * INNER];
__device__ bf16 g_k [ROWS * INNER];
__device__ bf16 g_v [ROWS * INNER];
__device__ float g_dots[BATCH * NHEAD * SSQ];
__device__ bf16 g_at[BATCH * NHEAD * SSQ];
__device__ bf16 g_o [ROWS * INNER];
__device__ bf16 g_m [ROWS * MLPDIM];
// cast weights (natural [k][n] layout, bf16)
__device__ bf16 g_wq [DEPTH * DIM * INNER];
__device__ bf16 g_wkv[DEPTH * DIM * 2 * INNER];
__device__ bf16 g_wo [DEPTH * INNER * DIM];
__device__ bf16 g_w1 [DEPTH * DIM * MLPDIM];
__device__ bf16 g_w2 [DEPTH * MLPDIM * DIM];

__device__ __forceinline__ float gelu_tanh(float x) {
    float x3 = x * x * x;
    return 0.5f * x * (1.0f + tanhf(0.7978845608028654f * (x + 0.044715f * x3)));
}

__device__ __forceinline__ void cp16(unsigned s, const void* g) {
    asm volatile("cp.async.cg.shared.global [%0], [%1], 16;\n" :: "r"(s), "l"(g));
}
__device__ __forceinline__ void cp_commit() {
    asm volatile("cp.async.commit_group;\n");
}
template<int N> __device__ __forceinline__ void cp_wait() {
    asm volatile("cp.async.wait_group %0;\n" :: "n"(N));
}
__device__ __forceinline__ void ldsm4(unsigned& r0, unsigned& r1, unsigned& r2,
                                      unsigned& r3, unsigned addr) {
    asm volatile("ldmatrix.sync.aligned.m8n8.x4.shared.b16 {%0,%1,%2,%3}, [%4];\n"
                 : "=r"(r0), "=r"(r1), "=r"(r2), "=r"(r3) : "r"(addr));
}
__device__ __forceinline__ void ldsm4t(unsigned& r0, unsigned& r1, unsigned& r2,
                                       unsigned& r3, unsigned addr) {
    asm volatile("ldmatrix.sync.aligned.m8n8.x4.trans.shared.b16 {%0,%1,%2,%3}, [%4];\n"
                 : "=r"(r0), "=r"(r1), "=r"(r2), "=r"(r3) : "r"(addr));
}
#define MMA16(d, a, b0, b1) \
    asm volatile("mma.sync.aligned.m16n8k16.row.col.f32.bf16.bf16.f32 " \
                 "{%0,%1,%2,%3},{%4,%5,%6,%7},{%8,%9},{%0,%1,%2,%3};\n" \
                 : "+f"(d[0]), "+f"(d[1]), "+f"(d[2]), "+f"(d[3])       \
                 : "r"(a[0]), "r"(a[1]), "r"(a[2]), "r"(a[3]), "r"(b0), "r"(b1))

// ---------------- elementwise cast f32 -> bf16 ----------------
__global__ __launch_bounds__(256) void wcast(const float* __restrict__ in,
                                             bf16* __restrict__ out, int n4) {
    int i = blockIdx.x * 256 + threadIdx.x;
    if (i < n4) {
        float4 v = ((const float4*)in)[i];
        __nv_bfloat162 p0, p1;
        p0.x = __float2bfloat16(v.x); p0.y = __float2bfloat16(v.y);
        p1.x = __float2bfloat16(v.z); p1.y = __float2bfloat16(v.w);
        ((__nv_bfloat162*)out)[2 * i] = p0;
        ((__nv_bfloat162*)out)[2 * i + 1] = p1;
    }
}

// ---------------- LayerNorm -> bf16 ----------------
__global__ __launch_bounds__(256) void ln_cast(const float* __restrict__ x,
                                               const float* __restrict__ scale,
                                               bf16* __restrict__ out) {
    int row = blockIdx.x;
    const float* xr = x + (size_t)row * DIM;
    int tid = threadIdx.x;
    float s = 0.f, s2 = 0.f;
    for (int c = tid; c < DIM; c += 256) { float v = xr[c]; s += v; s2 += v * v; }
    __shared__ float rs[256], rs2[256];
    rs[tid] = s; rs2[tid] = s2;
    __syncthreads();
    for (int off = 128; off > 0; off >>= 1) {
        if (tid < off) { rs[tid] += rs[tid + off]; rs2[tid] += rs2[tid + off]; }
        __syncthreads();
    }
    float mu = rs[0] * (1.0f / DIM);
    float var = rs2[0] * (1.0f / DIM) - mu * mu;
    float rstd = rsqrtf(var + EPS);
    for (int c = tid; c < DIM; c += 256)
        out[(size_t)row * DIM + c] = __float2bfloat16((xr[c] - mu) * rstd * scale[c]);
}

// ---------------- fused mix_pre -> softmax -> mix_post ----------------
__global__ __launch_bounds__(384) void attn_mix_softmax(
    const float* __restrict__ dots, const float* __restrict__ mp,
    const float* __restrict__ mq, bf16* __restrict__ at)
{
    __shared__ float S[NHEAD][SEQ];
    __shared__ float T[NHEAD][SEQ];
    int tid = threadIdx.x, lane = tid & 31, g = tid >> 5;
    int b = blockIdx.x >> 9, i = blockIdx.x & 511;
    const float* base = dots + ((size_t)(b * NHEAD) * SEQ + i) * SEQ;

    #pragma unroll
    for (int it = 0; it < 4; it++) {
        int idx = tid + it * 384;
        int h = idx >> 7, jq = (idx & 127) << 2;
        *(float4*)&S[h][jq] = *(const float4*)(base + (size_t)h * SSQ + jq);
    }
    __syncthreads();

    float mcol[NHEAD];
    #pragma unroll
    for (int h = 0; h < NHEAD; h++) mcol[h] = __ldg(&mp[h * NHEAD + g]);
    float v[16];
    float mx = -1e30f;
    #pragma unroll
    for (int k = 0; k < 16; k++) {
        int j = lane + k * 32;
        float a = 0.f;
        #pragma unroll
        for (int h = 0; h < NHEAD; h++) a += S[h][j] * mcol[h];
        v[k] = a; mx = fmaxf(mx, a);
    }
    #pragma unroll
    for (int off = 16; off > 0; off >>= 1)
        mx = fmaxf(mx, __shfl_xor_sync(0xffffffffu, mx, off));
    float s = 0.f;
    #pragma unroll
    for (int k = 0; k < 16; k++) { v[k] = __expf(v[k] - mx); s += v[k]; }
    #pragma unroll
    for (int off = 16; off > 0; off >>= 1)
        s += __shfl_xor_sync(0xffffffffu, s, off);
    float inv = 1.0f / s;
    #pragma unroll
    for (int k = 0; k < 16; k++) T[g][lane + k * 32] = v[k] * inv;
    __syncthreads();

    float qcol[NHEAD];
    #pragma unroll
    for (int h = 0; h < NHEAD; h++) qcol[h] = __ldg(&mq[h * NHEAD + g]);
    size_t ob = ((size_t)((b * NHEAD + g) * SEQ) + i) * SEQ;
    #pragma unroll
    for (int k = 0; k < 16; k++) {
        int j = lane + k * 32;
        float a = 0.f;
        #pragma unroll
        for (int h = 0; h < NHEAD; h++) a += T[h][j] * qcol[h];
        at[ob + j] = __float2bfloat16(a);
    }
}

// ---------------- single-bf16 tensor-core GEMM ----------------
// A[m][k] bf16. B: TB=0 -> [n][k] bf16; TB=1 -> [k][n] bf16 (ldmatrix.trans).
// epi: 0 f32 store*alpha   2 X += (v+bias)*LS   4 gelu(v+bias)->bf16   5 bf16 store
template<int BN, int WARPS_M, int WARPS_N, int TB>
__global__ __launch_bounds__(256) void tgemm1(
    const bf16* __restrict__ Ap, int lda, long sAb, long sAh,
    const bf16* __restrict__ Bp, int ldb, long sBb, long sBh,
    float* __restrict__ Cf, bf16* __restrict__ Cb,
    int ldc, long sCb, long sCh, const float* __restrict__ bias,
    int K, int nH, float alpha, int epi)
{
    constexpr int BM = 128, BK = 64, STAGES = 3;
    constexpr int RB_A = 144;                       // 128B data + 16B pad
    constexpr int RB_B = TB ? (BN * 2 + 16) : 144;
    constexpr unsigned OFF_B = BM * RB_A;
    constexpr unsigned B_BYTES = TB ? (BK * RB_B) : (BN * RB_B);
    constexpr unsigned STAGE = OFF_B + B_BYTES;
    constexpr int WM = BM / WARPS_M, WN = BN / WARPS_N;
    constexpr int MF = WM / 16, NF = WN / 8, NF2 = NF / 2;
    constexpr int TOT_A = BM * 8;
    constexpr int TOT_B = TB ? (BK * (BN / 8)) : (BN * 8);

    extern __shared__ __align__(16) char ds[];
    unsigned sb0 = (unsigned)__cvta_generic_to_shared(ds);

    int tid = threadIdx.x, lane = tid & 31, warp = tid >> 5;
    int wm = warp / WARPS_N, wn = warp % WARPS_N;
    int bz = blockIdx.z / nH, hz = blockIdx.z % nH;
    int row0 = blockIdx.y * BM, n0 = blockIdx.x * BN;

    const bf16* Ah = Ap + (size_t)bz * sAb + (size_t)hz * sAh + (size_t)row0 * lda;
    const bf16* Bh = Bp + (size_t)bz * sBb + (size_t)hz * sBh
                        + (TB ? (size_t)n0 : (size_t)n0 * ldb);

    const int KT = K / BK;

    auto load_stage = [&](int t) {
        unsigned sbm = sb0 + (unsigned)(t % STAGES) * STAGE;
        int k0 = t * BK;
        #pragma unroll
        for (int c = tid; c < TOT_A + TOT_B; c += 256) {
            if (c < TOT_A) {
                int r = c >> 3, q = c & 7;
                cp16(sbm + (unsigned)(r * RB_A + q * 16),
                     Ah + (size_t)r * lda + k0 + q * 8);
            } else if (TB) {
                int cc = c - TOT_A;
                int r = cc / (BN / 8), q = cc % (BN / 8);
                cp16(sbm + OFF_B + (unsigned)(r * RB_B + q * 16),
                     Bh + (size_t)(k0 + r) * ldb + q * 8);
            } else {
                int cc = c - TOT_A;
                int r = cc >> 3, q = cc & 7;
                cp16(sbm + OFF_B + (unsigned)(r * RB_B + q * 16),
                     Bh + (size_t)r * ldb + k0 + q * 8);
            }
        }
    };

    float acc[MF][NF][4] = {};

    #pragma unroll
    for (int s = 0; s < STAGES - 1; s++)
        if (s < KT) { load_stage(s); cp_commit(); }

    int arow = lane & 15;
    int acol = (lane >> 4) << 4;
    // non-trans B addressing
    int nrow = (lane & 7) | ((lane & 16) >> 1);
    int ncol = (lane & 8) ? 16 : 0;
    // trans B addressing
    int krow = lane & 15;
    int noff = (lane & 16) ? 16 : 0;   // byte offset (+8 cols)

    for (int t = 0; t < KT; t++) {
        if (t + 1 < KT) cp_wait<1>(); else cp_wait<0>();
        __syncthreads();
        if (t + STAGES - 1 < KT) { load_stage(t + STAGES - 1); cp_commit(); }

        unsigned sbm = sb0 + (unsigned)(t % STAGES) * STAGE;
        #pragma unroll
        for (int kk = 0; kk < BK / 16; kk++) {
            unsigned ah[MF][4], bh[NF2][4];
            #pragma unroll
            for (int mi = 0; mi < MF; mi++) {
                unsigned base = sbm + (unsigned)((wm * WM + mi * 16 + arow) * RB_A + kk * 32 + acol);
                ldsm4(ah[mi][0], ah[mi][1], ah[mi][2], ah[mi][3], base);
            }
            #pragma unroll
            for (int j = 0; j < NF2; j++) {
                if (TB) {
                    unsigned base = sbm + OFF_B
                        + (unsigned)((kk * 16 + krow) * RB_B + (wn * WN + j * 16) * 2 + noff);
                    ldsm4t(bh[j][0], bh[j][1], bh[j][2], bh[j][3], base);
                } else {
                    unsigned base = sbm + OFF_B
                        + (unsigned)((wn * WN + j * 16 + nrow) * RB_B + kk * 32 + ncol);
                    ldsm4(bh[j][0], bh[j][1], bh[j][2], bh[j][3], base);
                }
            }
            #pragma unroll
            for (int mi = 0; mi < MF; mi++)
                #pragma unroll
                for (int ni = 0; ni < NF; ni++) {
                    int j = ni >> 1, o = (ni & 1) * 2;
                    MMA16(acc[mi][ni], ah[mi], bh[j][o], bh[j][o + 1]);
                }
        }
    }

    // ---- epilogue ----
    float* Cfb = Cf ? Cf + (size_t)bz * sCb + (size_t)hz * sCh : nullptr;
    bf16* Cbb = Cb ? Cb + (size_t)bz * sCb + (size_t)hz * sCh : nullptr;

    #pragma unroll
    for (int mi = 0; mi < MF; mi++) {
        #pragma unroll
        for (int ni = 0; ni < NF; ni++) {
            int r0 = row0 + wm * WM + mi * 16 + (lane >> 2);
            int cn = n0 + wn * WN + ni * 8 + 2 * (lane & 3);
            #pragma unroll
            for (int half = 0; half < 2; half++) {
                int r = r0 + half * 8;
                float v0 = acc[mi][ni][half * 2 + 0] * alpha;
                float v1 = acc[mi][ni][half * 2 + 1] * alpha;
                size_t off = (size_t)r * ldc + cn;
                if (epi == 0) {
                    *(float2*)(Cfb + off) = make_float2(v0, v1);
                } else if (epi == 2) {
                    float2 old = *(float2*)(Cfb + off);
                    old.x += (v0 + bias[cn]) * LSCALE;
                    old.y += (v1 + bias[cn + 1]) * LSCALE;
                    *(float2*)(Cfb + off) = old;
                } else if (epi == 4) {
                    __nv_bfloat162 p;
                    p.x = __float2bfloat16(gelu_tanh(v0 + bias[cn]));
                    p.y = __float2bfloat16(gelu_tanh(v1 + bias[cn + 1]));
                    *(__nv_bfloat162*)(Cbb + off) = p;
                } else {   // 5
                    __nv_bfloat162 p;
                    p.x = __float2bfloat16(v0);
                    p.y = __float2bfloat16(v1);
                    *(__nv_bfloat162*)(Cbb + off) = p;
                }
            }
        }
    }
}

// ---------------- launch ----------------
extern "C" void kernel_launch(void* const* d_in, const int* in_sizes, int n_in,
                              void* d_out, int out_size) {
    const float* x_in     = (const float*)d_in[0];
    const float* ln1      = (const float*)d_in[1];
    const float* Wq       = (const float*)d_in[2];
    const float* Wkv      = (const float*)d_in[3];
    const float* mix_pre  = (const float*)d_in[4];
    const float* mix_post = (const float*)d_in[5];
    const float* Wo       = (const float*)d_in[6];
    const float* bo       = (const float*)d_in[7];
    const float* ln2      = (const float*)d_in[8];
    const float* W1       = (const float*)d_in[9];
    const float* b1       = (const float*)d_in[10];
    const float* W2       = (const float*)d_in[11];
    const float* b2       = (const float*)d_in[12];

    float* X = (float*)d_out;

    bf16 *h, *q, *k, *v, *at, *o, *m;
    bf16 *wq, *wkv, *wo, *w1, *w2;
    float* dots;
    cudaGetSymbolAddress((void**)&h,  g_h);
    cudaGetSymbolAddress((void**)&q,  g_q);
    cudaGetSymbolAddress((void**)&k,  g_k);
    cudaGetSymbolAddress((void**)&v,  g_v);
    cudaGetSymbolAddress((void**)&at, g_at);
    cudaGetSymbolAddress((void**)&o,  g_o);
    cudaGetSymbolAddress((void**)&m,  g_m);
    cudaGetSymbolAddress((void**)&wq,  g_wq);
    cudaGetSymbolAddress((void**)&wkv, g_wkv);
    cudaGetSymbolAddress((void**)&wo,  g_wo);
    cudaGetSymbolAddress((void**)&w1,  g_w1);
    cudaGetSymbolAddress((void**)&w2,  g_w2);
    cudaGetSymbolAddress((void**)&dots, g_dots);

    // smem sizes per template instantiation
    const int SM_T1_128 = 3 * (128 * 144 + 64 * (128 * 2 + 16));  // trans, BN=128: 107520
    const int SM_T0_128 = 3 * (128 * 144 + 128 * 144);            // non-trans, BN=128: 110592
    const int SM_T1_64  = 3 * (128 * 144 + 64 * (64 * 2 + 16));   // trans, BN=64: 82944
    cudaFuncSetAttribute((const void*)tgemm1<128, 2, 4, 1>,
                         cudaFuncAttributeMaxDynamicSharedMemorySize, SM_T1_128);
    cudaFuncSetAttribute((const void*)tgemm1<128, 2, 4, 0>,
                         cudaFuncAttributeMaxDynamicSharedMemorySize, SM_T0_128);
    cudaFuncSetAttribute((const void*)tgemm1<64, 4, 2, 1>,
                         cudaFuncAttributeMaxDynamicSharedMemorySize, SM_T1_64);

    cudaMemcpyAsync(X, x_in, (size_t)ROWS * DIM * sizeof(float),
                    cudaMemcpyDeviceToDevice);

    // ---- weight cast (pure elementwise; layout stays [k][n]) ----
    {
        int n4;
        n4 = DEPTH * DIM * INNER / 4;
        wcast<<<(n4 + 255) / 256, 256>>>(Wq, wq, n4);
        n4 = DEPTH * DIM * 2 * INNER / 4;
        wcast<<<(n4 + 255) / 256, 256>>>(Wkv, wkv, n4);
        n4 = DEPTH * INNER * DIM / 4;
        wcast<<<(n4 + 255) / 256, 256>>>(Wo, wo, n4);
        n4 = DEPTH * DIM * MLPDIM / 4;
        wcast<<<(n4 + 255) / 256, 256>>>(W1, w1, n4);
        n4 = DEPTH * MLPDIM * DIM / 4;
        wcast<<<(n4 + 255) / 256, 256>>>(W2, w2, n4);
    }

    for (int d = 0; d < DEPTH; d++) {
        size_t wo768 = (size_t)d * DIM * INNER;
        size_t wkvo  = (size_t)d * DIM * 2 * INNER;
        size_t w1o   = (size_t)d * DIM * MLPDIM;

        // ---- attention half ----
        ln_cast<<<ROWS, 256>>>(X, ln1 + d * DIM, h);

        // q = h @ Wq
        tgemm1<128, 2, 4, 1><<<dim3(INNER / 128, ROWS / 128, 1), 256, SM_T1_128>>>(
            h, DIM, 0, 0,
            wq + wo768, INNER, 0, 0,
            nullptr, q, INNER, 0, 0, nullptr,
            DIM, 1, 1.f, 5);
        // k = h @ Wk
        tgemm1<128, 2, 4, 1><<<dim3(INNER / 128, ROWS / 128, 1), 256, SM_T1_128>>>(
            h, DIM, 0, 0,
            wkv + wkvo, 2 * INNER, 0, 0,
            nullptr, k, INNER, 0, 0, nullptr,
            DIM, 1, 1.f, 5);
        // v = h @ Wv (natural [i][inner] layout)
        tgemm1<128, 2, 4, 1><<<dim3(INNER / 128, ROWS / 128, 1), 256, SM_T1_128>>>(
            h, DIM, 0, 0,
            wkv + wkvo + INNER, 2 * INNER, 0, 0,
            nullptr, v, INNER, 0, 0, nullptr,
            DIM, 1, 1.f, 5);

        // dots = scale * q @ k^T per (b,h)   (k is [j][d] = [n][k])
        tgemm1<128, 2, 4, 0><<<dim3(SEQ / 128, SEQ / 128, BATCH * NHEAD), 256, SM_T0_128>>>(
            q, INNER, (long)SEQ * INNER, DH,
            k, INNER, (long)SEQ * INNER, DH,
            dots, nullptr, SEQ, (long)NHEAD * SSQ, (long)SSQ, nullptr,
            DH, NHEAD, ATT_SCALE, 0);

        attn_mix_softmax<<<BATCH * SEQ, 384>>>(dots, mix_pre + d * NHEAD * NHEAD,
                                               mix_post + d * NHEAD * NHEAD, at);

        // o = attn @ v   (v natural [j][d] = [k][n] -> trans path)
        tgemm1<64, 4, 2, 1><<<dim3(1, SEQ / 128, BATCH * NHEAD), 256, SM_T1_64>>>(
            at, SEQ, (long)NHEAD * SSQ, (long)SSQ,
            v, INNER, (long)SEQ * INNER, (long)DH,
            nullptr, o, INNER, (long)SEQ * INNER, (long)DH, nullptr,
            SEQ, NHEAD, 1.f, 5);

        // X += (o @ Wo + bo) * LS
        tgemm1<128, 2, 4, 1><<<dim3(DIM / 128, ROWS / 128, 1), 256, SM_T1_128>>>(
            o, INNER, 0, 0,
            wo + wo768, DIM, 0, 0,
            X, nullptr, DIM, 0, 0, bo + d * DIM,
            INNER, 1, 1.f, 2);

        // ---- MLP half ----
        ln_cast<<<ROWS, 256>>>(X, ln2 + d * DIM, h);

        tgemm1<128, 2, 4, 1><<<dim3(MLPDIM / 128, ROWS / 128, 1), 256, SM_T1_128>>>(
            h, DIM, 0, 0,
            w1 + w1o, MLPDIM, 0, 0,
            nullptr, m, MLPDIM, 0, 0, b1 + d * MLPDIM,
            DIM, 1, 1.f, 4);

        tgemm1<128, 2, 4, 1><<<dim3(DIM / 128, ROWS / 128, 1), 256, SM_T1_128>>>(
            m, MLPDIM, 0, 0,
            w2 + w1o, DIM, 0, 0,
            X, nullptr, DIM, 0, 0, b2 + d * DIM,
            MLPDIM, 1, 1.f, 2);
    }
}

// round 11
// speedup vs baseline: 1.8466x; 1.0817x over previous
#include <cuda_runtime.h>
#include <cuda_bf16.h>
#include <math.h>
#include <stdint.h>

#define BATCH 8
#define SEQ 512
#define DIM 768
#define NHEAD 12
#define DH 64
#define INNER 768
#define MLPDIM 3072
#define DEPTH 4
#define ROWS (BATCH * SEQ)
#define LSCALE 0.1f
#define EPS 1e-5f
#define ATT_SCALE 0.125f
#define SSQ (SEQ * SEQ)
#define QKVN (3 * INNER)          // 2304

typedef __nv_bfloat16 bf16;

// ---------------- scratch (device globals) ----------------
__device__ bf16 g_h   [ROWS * DIM];
__device__ bf16 g_qkv [ROWS * QKVN];                 // q | k | v
__device__ bf16 g_db  [BATCH * NHEAD * SSQ];         // bf16 logits
__device__ bf16 g_at  [BATCH * NHEAD * SSQ];         // post-softmax attn
__device__ bf16 g_o   [ROWS * INNER];
__device__ bf16 g_m   [ROWS * MLPDIM];
// packed / cast weights ([k][n] layout)
__device__ bf16 g_wqkv[DEPTH * DIM * QKVN];
__device__ bf16 g_wo  [DEPTH * INNER * DIM];
__device__ bf16 g_w1  [DEPTH * DIM * MLPDIM];
__device__ bf16 g_w2  [DEPTH * MLPDIM * DIM];

__device__ __forceinline__ float gelu_tanh(float x) {
    float x3 = x * x * x;
    return 0.5f * x * (1.0f + tanhf(0.7978845608028654f * (x + 0.044715f * x3)));
}

__device__ __forceinline__ void cp16(unsigned s, const void* g) {
    asm volatile("cp.async.cg.shared.global [%0], [%1], 16;\n" :: "r"(s), "l"(g));
}
__device__ __forceinline__ void cp_commit() {
    asm volatile("cp.async.commit_group;\n");
}
template<int N> __device__ __forceinline__ void cp_wait() {
    asm volatile("cp.async.wait_group %0;\n" :: "n"(N));
}
__device__ __forceinline__ void ldsm4(unsigned& r0, unsigned& r1, unsigned& r2,
                                      unsigned& r3, unsigned addr) {
    asm volatile("ldmatrix.sync.aligned.m8n8.x4.shared.b16 {%0,%1,%2,%3}, [%4];\n"
                 : "=r"(r0), "=r"(r1), "=r"(r2), "=r"(r3) : "r"(addr));
}
__device__ __forceinline__ void ldsm4t(unsigned& r0, unsigned& r1, unsigned& r2,
                                       unsigned& r3, unsigned addr) {
    asm volatile("ldmatrix.sync.aligned.m8n8.x4.trans.shared.b16 {%0,%1,%2,%3}, [%4];\n"
                 : "=r"(r0), "=r"(r1), "=r"(r2), "=r"(r3) : "r"(addr));
}
#define MMA16(d, a, b0, b1) \
    asm volatile("mma.sync.aligned.m16n8k16.row.col.f32.bf16.bf16.f32 " \
                 "{%0,%1,%2,%3},{%4,%5,%6,%7},{%8,%9},{%0,%1,%2,%3};\n" \
                 : "+f"(d[0]), "+f"(d[1]), "+f"(d[2]), "+f"(d[3])       \
                 : "r"(a[0]), "r"(a[1]), "r"(a[2]), "r"(a[3]), "r"(b0), "r"(b1))

// ---------------- cast f32 -> bf16 with column offset (weight packing) ----
__global__ __launch_bounds__(256) void wcast_pad(const float* __restrict__ in,
                                                 bf16* __restrict__ out,
                                                 int rows, int nin, int nout, int col0) {
    int i = blockIdx.x * 256 + threadIdx.x;
    int tot = rows * (nin >> 2);
    if (i < tot) {
        int r = i / (nin >> 2), c4 = i % (nin >> 2);
        float4 v = *(const float4*)(in + (size_t)r * nin + c4 * 4);
        __nv_bfloat162 p0, p1;
        p0.x = __float2bfloat16(v.x); p0.y = __float2bfloat16(v.y);
        p1.x = __float2bfloat16(v.z); p1.y = __float2bfloat16(v.w);
        __nv_bfloat162* op = (__nv_bfloat162*)(out + (size_t)r * nout + col0 + c4 * 4);
        op[0] = p0; op[1] = p1;
    }
}

// ---------------- LayerNorm -> bf16 ----------------
__global__ __launch_bounds__(256) void ln_cast(const float* __restrict__ x,
                                               const float* __restrict__ scale,
                                               bf16* __restrict__ out) {
    int row = blockIdx.x;
    const float* xr = x + (size_t)row * DIM;
    int tid = threadIdx.x;
    float s = 0.f, s2 = 0.f;
    for (int c = tid; c < DIM; c += 256) { float v = xr[c]; s += v; s2 += v * v; }
    __shared__ float rs[256], rs2[256];
    rs[tid] = s; rs2[tid] = s2;
    __syncthreads();
    for (int off = 128; off > 0; off >>= 1) {
        if (tid < off) { rs[tid] += rs[tid + off]; rs2[tid] += rs2[tid + off]; }
        __syncthreads();
    }
    float mu = rs[0] * (1.0f / DIM);
    float var = rs2[0] * (1.0f / DIM) - mu * mu;
    float rstd = rsqrtf(var + EPS);
    for (int c = tid; c < DIM; c += 256)
        out[(size_t)row * DIM + c] = __float2bfloat16((xr[c] - mu) * rstd * scale[c]);
}

// ---------------- fused mix_pre -> softmax -> mix_post (bf16 in/out) -------
__global__ __launch_bounds__(384) void attn_mix_softmax(
    const bf16* __restrict__ dots, const float* __restrict__ mp,
    const float* __restrict__ mq, bf16* __restrict__ at)
{
    __shared__ float S[NHEAD][SEQ];
    __shared__ float T[NHEAD][SEQ];
    int tid = threadIdx.x, lane = tid & 31, g = tid >> 5;
    int b = blockIdx.x >> 9, i = blockIdx.x & 511;
    const bf16* base = dots + ((size_t)(b * NHEAD) * SEQ + i) * SEQ;

    // load 12 head-rows of 512 bf16 = 768 uint4 chunks
    #pragma unroll
    for (int it = 0; it < 2; it++) {
        int idx = tid + it * 384;                 // 0..767
        int h = idx >> 6, q = idx & 63;
        uint4 raw = *(const uint4*)(base + (size_t)h * SSQ + q * 8);
        const __nv_bfloat162* pp = (const __nv_bfloat162*)&raw;
        #pragma unroll
        for (int p = 0; p < 4; p++) {
            float2 f = __bfloat1622float2(pp[p]);
            S[h][q * 8 + 2 * p]     = f.x;
            S[h][q * 8 + 2 * p + 1] = f.y;
        }
    }
    __syncthreads();

    float mcol[NHEAD];
    #pragma unroll
    for (int h = 0; h < NHEAD; h++) mcol[h] = __ldg(&mp[h * NHEAD + g]);
    float v[16];
    float mx = -1e30f;
    #pragma unroll
    for (int k = 0; k < 16; k++) {
        int j = lane + k * 32;
        float a = 0.f;
        #pragma unroll
        for (int h = 0; h < NHEAD; h++) a += S[h][j] * mcol[h];
        v[k] = a; mx = fmaxf(mx, a);
    }
    #pragma unroll
    for (int off = 16; off > 0; off >>= 1)
        mx = fmaxf(mx, __shfl_xor_sync(0xffffffffu, mx, off));
    float s = 0.f;
    #pragma unroll
    for (int k = 0; k < 16; k++) { v[k] = __expf(v[k] - mx); s += v[k]; }
    #pragma unroll
    for (int off = 16; off > 0; off >>= 1)
        s += __shfl_xor_sync(0xffffffffu, s, off);
    float inv = 1.0f / s;
    #pragma unroll
    for (int k = 0; k < 16; k++) T[g][lane + k * 32] = v[k] * inv;
    __syncthreads();

    float qcol[NHEAD];
    #pragma unroll
    for (int h = 0; h < NHEAD; h++) qcol[h] = __ldg(&mq[h * NHEAD + g]);
    size_t ob = ((size_t)((b * NHEAD + g) * SEQ) + i) * SEQ;
    #pragma unroll
    for (int k = 0; k < 16; k++) {
        int j = lane + k * 32;
        float a = 0.f;
        #pragma unroll
        for (int h = 0; h < NHEAD; h++) a += T[h][j] * qcol[h];
        at[ob + j] = __float2bfloat16(a);
    }
}

// ---------------- single-bf16 tensor-core GEMM ----------------
// A[m][k] bf16. B: TB=0 -> [n][k]; TB=1 -> [k][n] (ldmatrix.trans).
// epi: 2 X += (v+bias)*LS (f32)   4 gelu(v+bias)->bf16   5 bf16 store (alpha)
template<int BN, int WARPS_M, int WARPS_N, int TB>
__global__ __launch_bounds__(256, 2) void tgemm1(
    const bf16* __restrict__ Ap, int lda, long sAb, long sAh,
    const bf16* __restrict__ Bp, int ldb, long sBb, long sBh,
    float* __restrict__ Cf, bf16* __restrict__ Cb,
    int ldc, long sCb, long sCh, const float* __restrict__ bias,
    int K, int nH, float alpha, int epi)
{
    constexpr int BM = 128, BK = 64, STAGES = 3;
    constexpr int RB_A = 144;
    constexpr int RB_B = TB ? (BN * 2 + 16) : 144;
    constexpr unsigned OFF_B = BM * RB_A;
    constexpr unsigned B_BYTES = TB ? (BK * RB_B) : (BN * RB_B);
    constexpr unsigned STAGE = OFF_B + B_BYTES;
    constexpr int WM = BM / WARPS_M, WN = BN / WARPS_N;
    constexpr int MF = WM / 16, NF = WN / 8, NF2 = NF / 2;
    constexpr int TOT_A = BM * 8;
    constexpr int TOT_B = TB ? (BK * (BN / 8)) : (BN * 8);

    extern __shared__ __align__(16) char ds[];
    unsigned sb0 = (unsigned)__cvta_generic_to_shared(ds);

    int tid = threadIdx.x, lane = tid & 31, warp = tid >> 5;
    int wm = warp / WARPS_N, wn = warp % WARPS_N;
    int bz = blockIdx.z / nH, hz = blockIdx.z % nH;
    int row0 = blockIdx.y * BM, n0 = blockIdx.x * BN;

    const bf16* Ah = Ap + (size_t)bz * sAb + (size_t)hz * sAh + (size_t)row0 * lda;
    const bf16* Bh = Bp + (size_t)bz * sBb + (size_t)hz * sBh
                        + (TB ? (size_t)n0 : (size_t)n0 * ldb);

    const int KT = K / BK;

    auto load_stage = [&](int t) {
        unsigned sbm = sb0 + (unsigned)(t % STAGES) * STAGE;
        int k0 = t * BK;
        #pragma unroll
        for (int c = tid; c < TOT_A + TOT_B; c += 256) {
            if (c < TOT_A) {
                int r = c >> 3, q = c & 7;
                cp16(sbm + (unsigned)(r * RB_A + q * 16),
                     Ah + (size_t)r * lda + k0 + q * 8);
            } else if (TB) {
                int cc = c - TOT_A;
                int r = cc / (BN / 8), q = cc % (BN / 8);
                cp16(sbm + OFF_B + (unsigned)(r * RB_B + q * 16),
                     Bh + (size_t)(k0 + r) * ldb + q * 8);
            } else {
                int cc = c - TOT_A;
                int r = cc >> 3, q = cc & 7;
                cp16(sbm + OFF_B + (unsigned)(r * RB_B + q * 16),
                     Bh + (size_t)r * ldb + k0 + q * 8);
            }
        }
    };

    float acc[MF][NF][4] = {};

    #pragma unroll
    for (int s = 0; s < STAGES - 1; s++)
        if (s < KT) { load_stage(s); cp_commit(); }

    int arow = lane & 15;
    int acol = (lane >> 4) << 4;
    int nrow = (lane & 7) | ((lane & 16) >> 1);
    int ncol = (lane & 8) ? 16 : 0;
    int krow = lane & 15;
    int noff = (lane & 16) ? 16 : 0;

    for (int t = 0; t < KT; t++) {
        if (t + 1 < KT) cp_wait<1>(); else cp_wait<0>();
        __syncthreads();
        if (t + STAGES - 1 < KT) { load_stage(t + STAGES - 1); cp_commit(); }

        unsigned sbm = sb0 + (unsigned)(t % STAGES) * STAGE;
        #pragma unroll
        for (int kk = 0; kk < BK / 16; kk++) {
            unsigned ah[MF][4], bh[NF2][4];
            #pragma unroll
            for (int mi = 0; mi < MF; mi++) {
                unsigned base = sbm + (unsigned)((wm * WM + mi * 16 + arow) * RB_A + kk * 32 + acol);
                ldsm4(ah[mi][0], ah[mi][1], ah[mi][2], ah[mi][3], base);
            }
            #pragma unroll
            for (int j = 0; j < NF2; j++) {
                if (TB) {
                    unsigned base = sbm + OFF_B
                        + (unsigned)((kk * 16 + krow) * RB_B + (wn * WN + j * 16) * 2 + noff);
                    ldsm4t(bh[j][0], bh[j][1], bh[j][2], bh[j][3], base);
                } else {
                    unsigned base = sbm + OFF_B
                        + (unsigned)((wn * WN + j * 16 + nrow) * RB_B + kk * 32 + ncol);
                    ldsm4(bh[j][0], bh[j][1], bh[j][2], bh[j][3], base);
                }
            }
            #pragma unroll
            for (int mi = 0; mi < MF; mi++)
                #pragma unroll
                for (int ni = 0; ni < NF; ni++) {
                    int j = ni >> 1, o = (ni & 1) * 2;
                    MMA16(acc[mi][ni], ah[mi], bh[j][o], bh[j][o + 1]);
                }
        }
    }

    // ---- epilogue ----
    float* Cfb = Cf ? Cf + (size_t)bz * sCb + (size_t)hz * sCh : nullptr;
    bf16* Cbb = Cb ? Cb + (size_t)bz * sCb + (size_t)hz * sCh : nullptr;

    #pragma unroll
    for (int mi = 0; mi < MF; mi++) {
        #pragma unroll
        for (int ni = 0; ni < NF; ni++) {
            int r0 = row0 + wm * WM + mi * 16 + (lane >> 2);
            int cn = n0 + wn * WN + ni * 8 + 2 * (lane & 3);
            #pragma unroll
            for (int half = 0; half < 2; half++) {
                int r = r0 + half * 8;
                float v0 = acc[mi][ni][half * 2 + 0] * alpha;
                float v1 = acc[mi][ni][half * 2 + 1] * alpha;
                size_t off = (size_t)r * ldc + cn;
                if (epi == 2) {
                    float2 old = *(float2*)(Cfb + off);
                    old.x += (v0 + bias[cn]) * LSCALE;
                    old.y += (v1 + bias[cn + 1]) * LSCALE;
                    *(float2*)(Cfb + off) = old;
                } else if (epi == 4) {
                    __nv_bfloat162 p;
                    p.x = __float2bfloat16(gelu_tanh(v0 + bias[cn]));
                    p.y = __float2bfloat16(gelu_tanh(v1 + bias[cn + 1]));
                    *(__nv_bfloat162*)(Cbb + off) = p;
                } else {   // 5
                    __nv_bfloat162 p;
                    p.x = __float2bfloat16(v0);
                    p.y = __float2bfloat16(v1);
                    *(__nv_bfloat162*)(Cbb + off) = p;
                }
            }
        }
    }
}

// ---------------- launch ----------------
extern "C" void kernel_launch(void* const* d_in, const int* in_sizes, int n_in,
                              void* d_out, int out_size) {
    const float* x_in     = (const float*)d_in[0];
    const float* ln1      = (const float*)d_in[1];
    const float* Wq       = (const float*)d_in[2];
    const float* Wkv      = (const float*)d_in[3];
    const float* mix_pre  = (const float*)d_in[4];
    const float* mix_post = (const float*)d_in[5];
    const float* Wo       = (const float*)d_in[6];
    const float* bo       = (const float*)d_in[7];
    const float* ln2      = (const float*)d_in[8];
    const float* W1       = (const float*)d_in[9];
    const float* b1       = (const float*)d_in[10];
    const float* W2       = (const float*)d_in[11];
    const float* b2       = (const float*)d_in[12];

    float* X = (float*)d_out;

    bf16 *h, *qkv, *db, *at, *o, *m;
    bf16 *wqkv, *wo, *w1, *w2;
    cudaGetSymbolAddress((void**)&h,   g_h);
    cudaGetSymbolAddress((void**)&qkv, g_qkv);
    cudaGetSymbolAddress((void**)&db,  g_db);
    cudaGetSymbolAddress((void**)&at,  g_at);
    cudaGetSymbolAddress((void**)&o,   g_o);
    cudaGetSymbolAddress((void**)&m,   g_m);
    cudaGetSymbolAddress((void**)&wqkv, g_wqkv);
    cudaGetSymbolAddress((void**)&wo,   g_wo);
    cudaGetSymbolAddress((void**)&w1,   g_w1);
    cudaGetSymbolAddress((void**)&w2,   g_w2);

    const int SM_T1_128 = 3 * (128 * 144 + 64 * (128 * 2 + 16));  // 107520
    const int SM_T0_128 = 3 * (128 * 144 + 128 * 144);            // 110592
    const int SM_T1_64  = 3 * (128 * 144 + 64 * (64 * 2 + 16));   // 82944
    cudaFuncSetAttribute((const void*)tgemm1<128, 2, 4, 1>,
                         cudaFuncAttributeMaxDynamicSharedMemorySize, SM_T1_128);
    cudaFuncSetAttribute((const void*)tgemm1<128, 2, 4, 0>,
                         cudaFuncAttributeMaxDynamicSharedMemorySize, SM_T0_128);
    cudaFuncSetAttribute((const void*)tgemm1<64, 4, 2, 1>,
                         cudaFuncAttributeMaxDynamicSharedMemorySize, SM_T1_64);

    cudaMemcpyAsync(X, x_in, (size_t)ROWS * DIM * sizeof(float),
                    cudaMemcpyDeviceToDevice);

    // ---- weight cast + pack (wq|wkv -> wqkv), plain casts for the rest ----
    {
        int tot;
        tot = DEPTH * DIM * (INNER / 4);            // Wq -> cols [0,768)
        wcast_pad<<<(tot + 255) / 256, 256>>>(Wq, wqkv, DEPTH * DIM, INNER, QKVN, 0);
        tot = DEPTH * DIM * (2 * INNER / 4);        // Wkv -> cols [768,2304)
        wcast_pad<<<(tot + 255) / 256, 256>>>(Wkv, wqkv, DEPTH * DIM, 2 * INNER, QKVN, INNER);
        tot = DEPTH * INNER * (DIM / 4);
        wcast_pad<<<(tot + 255) / 256, 256>>>(Wo, wo, DEPTH * INNER, DIM, DIM, 0);
        tot = DEPTH * DIM * (MLPDIM / 4);
        wcast_pad<<<(tot + 255) / 256, 256>>>(W1, w1, DEPTH * DIM, MLPDIM, MLPDIM, 0);
        tot = DEPTH * MLPDIM * (DIM / 4);
        wcast_pad<<<(tot + 255) / 256, 256>>>(W2, w2, DEPTH * MLPDIM, DIM, DIM, 0);
    }

    for (int d = 0; d < DEPTH; d++) {
        size_t wqkvo = (size_t)d * DIM * QKVN;
        size_t woo   = (size_t)d * INNER * DIM;
        size_t w1o   = (size_t)d * DIM * MLPDIM;

        // ---- attention half ----
        ln_cast<<<ROWS, 256>>>(X, ln1 + d * DIM, h);

        // qkv = h @ [Wq|Wk|Wv]   (one GEMM, N=2304)
        tgemm1<128, 2, 4, 1><<<dim3(QKVN / 128, ROWS / 128, 1), 256, SM_T1_128>>>(
            h, DIM, 0, 0,
            wqkv + wqkvo, QKVN, 0, 0,
            nullptr, qkv, QKVN, 0, 0, nullptr,
            DIM, 1, 1.f, 5);

        // dots(bf16) = scale * q @ k^T per (b,h)
        tgemm1<128, 2, 4, 0><<<dim3(SEQ / 128, SEQ / 128, BATCH * NHEAD), 256, SM_T0_128>>>(
            qkv, QKVN, (long)SEQ * QKVN, DH,
            qkv + INNER, QKVN, (long)SEQ * QKVN, DH,
            nullptr, db, SEQ, (long)NHEAD * SSQ, (long)SSQ, nullptr,
            DH, NHEAD, ATT_SCALE, 5);

        attn_mix_softmax<<<BATCH * SEQ, 384>>>(db, mix_pre + d * NHEAD * NHEAD,
                                               mix_post + d * NHEAD * NHEAD, at);

        // o = attn @ v   (v natural [j][d] in qkv -> trans path)
        tgemm1<64, 4, 2, 1><<<dim3(1, SEQ / 128, BATCH * NHEAD), 256, SM_T1_64>>>(
            at, SEQ, (long)NHEAD * SSQ, (long)SSQ,
            qkv + 2 * INNER, QKVN, (long)SEQ * QKVN, (long)DH,
            nullptr, o, INNER, (long)SEQ * INNER, (long)DH, nullptr,
            SEQ, NHEAD, 1.f, 5);

        // X += (o @ Wo + bo) * LS
        tgemm1<128, 2, 4, 1><<<dim3(DIM / 128, ROWS / 128, 1), 256, SM_T1_128>>>(
            o, INNER, 0, 0,
            wo + woo, DIM, 0, 0,
            X, nullptr, DIM, 0, 0, bo + d * DIM,
            INNER, 1, 1.f, 2);

        // ---- MLP half ----
        ln_cast<<<ROWS, 256>>>(X, ln2 + d * DIM, h);

        tgemm1<128, 2, 4, 1><<<dim3(MLPDIM / 128, ROWS / 128, 1), 256, SM_T1_128>>>(
            h, DIM, 0, 0,
            w1 + w1o, MLPDIM, 0, 0,
            nullptr, m, MLPDIM, 0, 0, b1 + d * MLPDIM,
            DIM, 1, 1.f, 4);

        tgemm1<128, 2, 4, 1><<<dim3(DIM / 128, ROWS / 128, 1), 256, SM_T1_128>>>(
            m, MLPDIM, 0, 0,
            w2 + w1o, DIM, 0, 0,
            X, nullptr, DIM, 0, 0, b2 + d * DIM,
            MLPDIM, 1, 1.f, 2);
    }
}

// round 12
// speedup vs baseline: 1.8833x; 1.0199x over previous
#include <cuda_runtime.h>
#include <cuda_bf16.h>
#include <math.h>
#include <stdint.h>

#define BATCH 8
#define SEQ 512
#define DIM 768
#define NHEAD 12
#define DH 64
#define INNER 768
#define MLPDIM 3072
#define DEPTH 4
#define ROWS (BATCH * SEQ)
#define LSCALE 0.1f
#define EPS 1e-5f
#define ATT_SCALE 0.125f
#define SSQ (SEQ * SEQ)
#define QKVN (3 * INNER)          // 2304

typedef __nv_bfloat16 bf16;

// ---------------- scratch (device globals) ----------------
__device__ bf16 g_h   [ROWS * DIM];
__device__ bf16 g_qkv [ROWS * QKVN];                 // q | k | v
__device__ bf16 g_db  [BATCH * NHEAD * SSQ];         // bf16 logits
__device__ bf16 g_at  [BATCH * NHEAD * SSQ];         // post-softmax attn
__device__ bf16 g_o   [ROWS * INNER];
__device__ bf16 g_m   [ROWS * MLPDIM];
// packed / cast weights ([k][n] layout)
__device__ bf16 g_wqkv[DEPTH * DIM * QKVN];
__device__ bf16 g_wo  [DEPTH * INNER * DIM];
__device__ bf16 g_w1  [DEPTH * DIM * MLPDIM];
__device__ bf16 g_w2  [DEPTH * MLPDIM * DIM];

__device__ __forceinline__ float gelu_tanh(float x) {
    float x3 = x * x * x;
    return 0.5f * x * (1.0f + tanhf(0.7978845608028654f * (x + 0.044715f * x3)));
}

__device__ __forceinline__ void cp16(unsigned s, const void* g) {
    asm volatile("cp.async.cg.shared.global [%0], [%1], 16;\n" :: "r"(s), "l"(g));
}
__device__ __forceinline__ void cp_commit() {
    asm volatile("cp.async.commit_group;\n");
}
template<int N> __device__ __forceinline__ void cp_wait() {
    asm volatile("cp.async.wait_group %0;\n" :: "n"(N));
}
__device__ __forceinline__ void ldsm4(unsigned& r0, unsigned& r1, unsigned& r2,
                                      unsigned& r3, unsigned addr) {
    asm volatile("ldmatrix.sync.aligned.m8n8.x4.shared.b16 {%0,%1,%2,%3}, [%4];\n"
                 : "=r"(r0), "=r"(r1), "=r"(r2), "=r"(r3) : "r"(addr));
}
__device__ __forceinline__ void ldsm4t(unsigned& r0, unsigned& r1, unsigned& r2,
                                       unsigned& r3, unsigned addr) {
    asm volatile("ldmatrix.sync.aligned.m8n8.x4.trans.shared.b16 {%0,%1,%2,%3}, [%4];\n"
                 : "=r"(r0), "=r"(r1), "=r"(r2), "=r"(r3) : "r"(addr));
}
#define MMA16(d, a, b0, b1) \
    asm volatile("mma.sync.aligned.m16n8k16.row.col.f32.bf16.bf16.f32 " \
                 "{%0,%1,%2,%3},{%4,%5,%6,%7},{%8,%9},{%0,%1,%2,%3};\n" \
                 : "+f"(d[0]), "+f"(d[1]), "+f"(d[2]), "+f"(d[3])       \
                 : "r"(a[0]), "r"(a[1]), "r"(a[2]), "r"(a[3]), "r"(b0), "r"(b1))

// ---------------- cast f32 -> bf16 with column offset (weight packing) ----
__global__ __launch_bounds__(256) void wcast_pad(const float* __restrict__ in,
                                                 bf16* __restrict__ out,
                                                 int rows, int nin, int nout, int col0) {
    int i = blockIdx.x * 256 + threadIdx.x;
    int tot = rows * (nin >> 2);
    if (i < tot) {
        int r = i / (nin >> 2), c4 = i % (nin >> 2);
        float4 v = *(const float4*)(in + (size_t)r * nin + c4 * 4);
        __nv_bfloat162 p0, p1;
        p0.x = __float2bfloat16(v.x); p0.y = __float2bfloat16(v.y);
        p1.x = __float2bfloat16(v.z); p1.y = __float2bfloat16(v.w);
        __nv_bfloat162* op = (__nv_bfloat162*)(out + (size_t)r * nout + col0 + c4 * 4);
        op[0] = p0; op[1] = p1;
    }
}

// ---------------- LayerNorm -> bf16 ----------------
__global__ __launch_bounds__(256) void ln_cast(const float* __restrict__ x,
                                               const float* __restrict__ scale,
                                               bf16* __restrict__ out) {
    int row = blockIdx.x;
    const float* xr = x + (size_t)row * DIM;
    int tid = threadIdx.x;
    float s = 0.f, s2 = 0.f;
    for (int c = tid; c < DIM; c += 256) { float v = xr[c]; s += v; s2 += v * v; }
    __shared__ float rs[256], rs2[256];
    rs[tid] = s; rs2[tid] = s2;
    __syncthreads();
    for (int off = 128; off > 0; off >>= 1) {
        if (tid < off) { rs[tid] += rs[tid + off]; rs2[tid] += rs2[tid + off]; }
        __syncthreads();
    }
    float mu = rs[0] * (1.0f / DIM);
    float var = rs2[0] * (1.0f / DIM) - mu * mu;
    float rstd = rsqrtf(var + EPS);
    for (int c = tid; c < DIM; c += 256)
        out[(size_t)row * DIM + c] = __float2bfloat16((xr[c] - mu) * rstd * scale[c]);
}

// ---------------- fused mix_pre -> softmax -> mix_post (bf16 in/out) -------
__global__ __launch_bounds__(384) void attn_mix_softmax(
    const bf16* __restrict__ dots, const float* __restrict__ mp,
    const float* __restrict__ mq, bf16* __restrict__ at)
{
    __shared__ float S[NHEAD][SEQ];
    __shared__ float T[NHEAD][SEQ];
    int tid = threadIdx.x, lane = tid & 31, g = tid >> 5;
    int b = blockIdx.x >> 9, i = blockIdx.x & 511;
    const bf16* base = dots + ((size_t)(b * NHEAD) * SEQ + i) * SEQ;

    #pragma unroll
    for (int it = 0; it < 2; it++) {
        int idx = tid + it * 384;                 // 0..767
        int h = idx >> 6, q = idx & 63;
        uint4 raw = *(const uint4*)(base + (size_t)h * SSQ + q * 8);
        const __nv_bfloat162* pp = (const __nv_bfloat162*)&raw;
        #pragma unroll
        for (int p = 0; p < 4; p++) {
            float2 f = __bfloat1622float2(pp[p]);
            S[h][q * 8 + 2 * p]     = f.x;
            S[h][q * 8 + 2 * p + 1] = f.y;
        }
    }
    __syncthreads();

    float mcol[NHEAD];
    #pragma unroll
    for (int h = 0; h < NHEAD; h++) mcol[h] = __ldg(&mp[h * NHEAD + g]);
    float v[16];
    float mx = -1e30f;
    #pragma unroll
    for (int k = 0; k < 16; k++) {
        int j = lane + k * 32;
        float a = 0.f;
        #pragma unroll
        for (int h = 0; h < NHEAD; h++) a += S[h][j] * mcol[h];
        v[k] = a; mx = fmaxf(mx, a);
    }
    #pragma unroll
    for (int off = 16; off > 0; off >>= 1)
        mx = fmaxf(mx, __shfl_xor_sync(0xffffffffu, mx, off));
    float s = 0.f;
    #pragma unroll
    for (int k = 0; k < 16; k++) { v[k] = __expf(v[k] - mx); s += v[k]; }
    #pragma unroll
    for (int off = 16; off > 0; off >>= 1)
        s += __shfl_xor_sync(0xffffffffu, s, off);
    float inv = 1.0f / s;
    #pragma unroll
    for (int k = 0; k < 16; k++) T[g][lane + k * 32] = v[k] * inv;
    __syncthreads();

    float qcol[NHEAD];
    #pragma unroll
    for (int h = 0; h < NHEAD; h++) qcol[h] = __ldg(&mq[h * NHEAD + g]);
    size_t ob = ((size_t)((b * NHEAD + g) * SEQ) + i) * SEQ;
    #pragma unroll
    for (int k = 0; k < 16; k++) {
        int j = lane + k * 32;
        float a = 0.f;
        #pragma unroll
        for (int h = 0; h < NHEAD; h++) a += T[h][j] * qcol[h];
        at[ob + j] = __float2bfloat16(a);
    }
}

// ---------------- single-bf16 tensor-core GEMM ----------------
// A[m][k] bf16. B: TB=0 -> [n][k]; TB=1 -> [k][n] (ldmatrix.trans).
// epi: 2 X += (v+bias)*LS (f32)   4 gelu(v+bias)->bf16   5 bf16 store (alpha)
template<int BN, int WARPS_M, int WARPS_N, int TB>
__global__ __launch_bounds__(256, 2) void tgemm1(
    const bf16* __restrict__ Ap, int lda, long sAb, long sAh,
    const bf16* __restrict__ Bp, int ldb, long sBb, long sBh,
    float* __restrict__ Cf, bf16* __restrict__ Cb,
    int ldc, long sCb, long sCh, const float* __restrict__ bias,
    int K, int nH, float alpha, int epi)
{
    constexpr int BM = 128, BK = 64, STAGES = 3;
    constexpr int RB_A = 144;
    constexpr int RB_B = TB ? (BN * 2 + 16) : 144;
    constexpr unsigned OFF_B = BM * RB_A;
    constexpr unsigned B_BYTES = TB ? (BK * RB_B) : (BN * RB_B);
    constexpr unsigned STAGE = OFF_B + B_BYTES;
    constexpr int WM = BM / WARPS_M, WN = BN / WARPS_N;
    constexpr int MF = WM / 16, NF = WN / 8, NF2 = NF / 2;
    constexpr int TOT_A = BM * 8;
    constexpr int TOT_B = TB ? (BK * (BN / 8)) : (BN * 8);

    extern __shared__ __align__(16) char ds[];
    unsigned sb0 = (unsigned)__cvta_generic_to_shared(ds);

    int tid = threadIdx.x, lane = tid & 31, warp = tid >> 5;
    int wm = warp / WARPS_N, wn = warp % WARPS_N;
    int bz = blockIdx.z / nH, hz = blockIdx.z % nH;
    int row0 = blockIdx.y * BM, n0 = blockIdx.x * BN;

    const bf16* Ah = Ap + (size_t)bz * sAb + (size_t)hz * sAh + (size_t)row0 * lda;
    const bf16* Bh = Bp + (size_t)bz * sBb + (size_t)hz * sBh
                        + (TB ? (size_t)n0 : (size_t)n0 * ldb);

    const int KT = K / BK;

    auto load_stage = [&](int t) {
        unsigned sbm = sb0 + (unsigned)(t % STAGES) * STAGE;
        int k0 = t * BK;
        #pragma unroll
        for (int c = tid; c < TOT_A + TOT_B; c += 256) {
            if (c < TOT_A) {
                int r = c >> 3, q = c & 7;
                cp16(sbm + (unsigned)(r * RB_A + q * 16),
                     Ah + (size_t)r * lda + k0 + q * 8);
            } else if (TB) {
                int cc = c - TOT_A;
                int r = cc / (BN / 8), q = cc % (BN / 8);
                cp16(sbm + OFF_B + (unsigned)(r * RB_B + q * 16),
                     Bh + (size_t)(k0 + r) * ldb + q * 8);
            } else {
                int cc = c - TOT_A;
                int r = cc >> 3, q = cc & 7;
                cp16(sbm + OFF_B + (unsigned)(r * RB_B + q * 16),
                     Bh + (size_t)r * ldb + k0 + q * 8);
            }
        }
    };

    float acc[MF][NF][4] = {};

    #pragma unroll
    for (int s = 0; s < STAGES - 1; s++)
        if (s < KT) { load_stage(s); cp_commit(); }

    int arow = lane & 15;
    int acol = (lane >> 4) << 4;
    int nrow = (lane & 7) | ((lane & 16) >> 1);
    int ncol = (lane & 8) ? 16 : 0;
    int krow = lane & 15;
    int noff = (lane & 16) ? 16 : 0;

    for (int t = 0; t < KT; t++) {
        if (t + 1 < KT) cp_wait<1>(); else cp_wait<0>();
        __syncthreads();
        if (t + STAGES - 1 < KT) { load_stage(t + STAGES - 1); cp_commit(); }

        unsigned sbm = sb0 + (unsigned)(t % STAGES) * STAGE;
        #pragma unroll
        for (int kk = 0; kk < BK / 16; kk++) {
            unsigned ah[MF][4], bh[NF2][4];
            #pragma unroll
            for (int mi = 0; mi < MF; mi++) {
                unsigned base = sbm + (unsigned)((wm * WM + mi * 16 + arow) * RB_A + kk * 32 + acol);
                ldsm4(ah[mi][0], ah[mi][1], ah[mi][2], ah[mi][3], base);
            }
            #pragma unroll
            for (int j = 0; j < NF2; j++) {
                if (TB) {
                    unsigned base = sbm + OFF_B
                        + (unsigned)((kk * 16 + krow) * RB_B + (wn * WN + j * 16) * 2 + noff);
                    ldsm4t(bh[j][0], bh[j][1], bh[j][2], bh[j][3], base);
                } else {
                    unsigned base = sbm + OFF_B
                        + (unsigned)((wn * WN + j * 16 + nrow) * RB_B + kk * 32 + ncol);
                    ldsm4(bh[j][0], bh[j][1], bh[j][2], bh[j][3], base);
                }
            }
            #pragma unroll
            for (int mi = 0; mi < MF; mi++)
                #pragma unroll
                for (int ni = 0; ni < NF; ni++) {
                    int j = ni >> 1, o = (ni & 1) * 2;
                    MMA16(acc[mi][ni], ah[mi], bh[j][o], bh[j][o + 1]);
                }
        }
    }

    // ---- epilogue ----
    float* Cfb = Cf ? Cf + (size_t)bz * sCb + (size_t)hz * sCh : nullptr;
    bf16* Cbb = Cb ? Cb + (size_t)bz * sCb + (size_t)hz * sCh : nullptr;

    #pragma unroll
    for (int mi = 0; mi < MF; mi++) {
        #pragma unroll
        for (int ni = 0; ni < NF; ni++) {
            int r0 = row0 + wm * WM + mi * 16 + (lane >> 2);
            int cn = n0 + wn * WN + ni * 8 + 2 * (lane & 3);
            #pragma unroll
            for (int half = 0; half < 2; half++) {
                int r = r0 + half * 8;
                float v0 = acc[mi][ni][half * 2 + 0] * alpha;
                float v1 = acc[mi][ni][half * 2 + 1] * alpha;
                size_t off = (size_t)r * ldc + cn;
                if (epi == 2) {
                    float2 old = *(float2*)(Cfb + off);
                    old.x += (v0 + bias[cn]) * LSCALE;
                    old.y += (v1 + bias[cn + 1]) * LSCALE;
                    *(float2*)(Cfb + off) = old;
                } else if (epi == 4) {
                    __nv_bfloat162 p;
                    p.x = __float2bfloat16(gelu_tanh(v0 + bias[cn]));
                    p.y = __float2bfloat16(gelu_tanh(v1 + bias[cn + 1]));
                    *(__nv_bfloat162*)(Cbb + off) = p;
                } else {   // 5
                    __nv_bfloat162 p;
                    p.x = __float2bfloat16(v0);
                    p.y = __float2bfloat16(v1);
                    *(__nv_bfloat162*)(Cbb + off) = p;
                }
            }
        }
    }
}

// ---------------- launch ----------------
extern "C" void kernel_launch(void* const* d_in, const int* in_sizes, int n_in,
                              void* d_out, int out_size) {
    const float* x_in     = (const float*)d_in[0];
    const float* ln1      = (const float*)d_in[1];
    const float* Wq       = (const float*)d_in[2];
    const float* Wkv      = (const float*)d_in[3];
    const float* mix_pre  = (const float*)d_in[4];
    const float* mix_post = (const float*)d_in[5];
    const float* Wo       = (const float*)d_in[6];
    const float* bo       = (const float*)d_in[7];
    const float* ln2      = (const float*)d_in[8];
    const float* W1       = (const float*)d_in[9];
    const float* b1       = (const float*)d_in[10];
    const float* W2       = (const float*)d_in[11];
    const float* b2       = (const float*)d_in[12];

    float* X = (float*)d_out;

    bf16 *h, *qkv, *db, *at, *o, *m;
    bf16 *wqkv, *wo, *w1, *w2;
    cudaGetSymbolAddress((void**)&h,   g_h);
    cudaGetSymbolAddress((void**)&qkv, g_qkv);
    cudaGetSymbolAddress((void**)&db,  g_db);
    cudaGetSymbolAddress((void**)&at,  g_at);
    cudaGetSymbolAddress((void**)&o,   g_o);
    cudaGetSymbolAddress((void**)&m,   g_m);
    cudaGetSymbolAddress((void**)&wqkv, g_wqkv);
    cudaGetSymbolAddress((void**)&wo,   g_wo);
    cudaGetSymbolAddress((void**)&w1,   g_w1);
    cudaGetSymbolAddress((void**)&w2,   g_w2);

    const int SM_T1_128 = 3 * (128 * 144 + 64 * (128 * 2 + 16));  // 107520
    const int SM_T0_128 = 3 * (128 * 144 + 128 * 144);            // 110592
    const int SM_T1_64  = 3 * (128 * 144 + 64 * (64 * 2 + 16));   // 82944
    cudaFuncSetAttribute((const void*)tgemm1<128, 2, 4, 1>,
                         cudaFuncAttributeMaxDynamicSharedMemorySize, SM_T1_128);
    cudaFuncSetAttribute((const void*)tgemm1<128, 2, 4, 0>,
                         cudaFuncAttributeMaxDynamicSharedMemorySize, SM_T0_128);
    cudaFuncSetAttribute((const void*)tgemm1<64, 4, 2, 1>,
                         cudaFuncAttributeMaxDynamicSharedMemorySize, SM_T1_64);

    cudaMemcpyAsync(X, x_in, (size_t)ROWS * DIM * sizeof(float),
                    cudaMemcpyDeviceToDevice);

    // ---- weight cast + pack (wq|wkv -> wqkv), plain casts for the rest ----
    {
        int tot;
        tot = DEPTH * DIM * (INNER / 4);            // Wq -> cols [0,768)
        wcast_pad<<<(tot + 255) / 256, 256>>>(Wq, wqkv, DEPTH * DIM, INNER, QKVN, 0);
        tot = DEPTH * DIM * (2 * INNER / 4);        // Wkv -> cols [768,2304)
        wcast_pad<<<(tot + 255) / 256, 256>>>(Wkv, wqkv, DEPTH * DIM, 2 * INNER, QKVN, INNER);
        tot = DEPTH * INNER * (DIM / 4);
        wcast_pad<<<(tot + 255) / 256, 256>>>(Wo, wo, DEPTH * INNER, DIM, DIM, 0);
        tot = DEPTH * DIM * (MLPDIM / 4);
        wcast_pad<<<(tot + 255) / 256, 256>>>(W1, w1, DEPTH * DIM, MLPDIM, MLPDIM, 0);
        tot = DEPTH * MLPDIM * (DIM / 4);
        wcast_pad<<<(tot + 255) / 256, 256>>>(W2, w2, DEPTH * MLPDIM, DIM, DIM, 0);
    }

    for (int d = 0; d < DEPTH; d++) {
        size_t wqkvo = (size_t)d * DIM * QKVN;
        size_t woo   = (size_t)d * INNER * DIM;
        size_t w1o   = (size_t)d * DIM * MLPDIM;

        // ---- attention half ----
        ln_cast<<<ROWS, 256>>>(X, ln1 + d * DIM, h);

        // qkv = h @ [Wq|Wk|Wv]   (one GEMM, N=2304, ~1.95 waves)
        tgemm1<128, 2, 4, 1><<<dim3(QKVN / 128, ROWS / 128, 1), 256, SM_T1_128>>>(
            h, DIM, 0, 0,
            wqkv + wqkvo, QKVN, 0, 0,
            nullptr, qkv, QKVN, 0, 0, nullptr,
            DIM, 1, 1.f, 5);

        // dots(bf16) = scale * q @ k^T per (b,h)
        tgemm1<128, 2, 4, 0><<<dim3(SEQ / 128, SEQ / 128, BATCH * NHEAD), 256, SM_T0_128>>>(
            qkv, QKVN, (long)SEQ * QKVN, DH,
            qkv + INNER, QKVN, (long)SEQ * QKVN, DH,
            nullptr, db, SEQ, (long)NHEAD * SSQ, (long)SSQ, nullptr,
            DH, NHEAD, ATT_SCALE, 5);

        attn_mix_softmax<<<BATCH * SEQ, 384>>>(db, mix_pre + d * NHEAD * NHEAD,
                                               mix_post + d * NHEAD * NHEAD, at);

        // o = attn @ v   (v natural [j][d] in qkv -> trans path)
        tgemm1<64, 4, 2, 1><<<dim3(1, SEQ / 128, BATCH * NHEAD), 256, SM_T1_64>>>(
            at, SEQ, (long)NHEAD * SSQ, (long)SSQ,
            qkv + 2 * INNER, QKVN, (long)SEQ * QKVN, (long)DH,
            nullptr, o, INNER, (long)SEQ * INNER, (long)DH, nullptr,
            SEQ, NHEAD, 1.f, 5);

        // X += (o @ Wo + bo) * LS   — BN=64: 384 CTAs = 1.3 waves (was 0.65)
        tgemm1<64, 4, 2, 1><<<dim3(DIM / 64, ROWS / 128, 1), 256, SM_T1_64>>>(
            o, INNER, 0, 0,
            wo + woo, DIM, 0, 0,
            X, nullptr, DIM, 0, 0, bo + d * DIM,
            INNER, 1, 1.f, 2);

        // ---- MLP half ----
        ln_cast<<<ROWS, 256>>>(X, ln2 + d * DIM, h);

        tgemm1<128, 2, 4, 1><<<dim3(MLPDIM / 128, ROWS / 128, 1), 256, SM_T1_128>>>(
            h, DIM, 0, 0,
            w1 + w1o, MLPDIM, 0, 0,
            nullptr, m, MLPDIM, 0, 0, b1 + d * MLPDIM,
            DIM, 1, 1.f, 4);

        // X += (gelu_out @ W2 + b2) * LS   — BN=64: 384 CTAs = 1.3 waves
        tgemm1<64, 4, 2, 1><<<dim3(DIM / 64, ROWS / 128, 1), 256, SM_T1_64>>>(
            m, MLPDIM, 0, 0,
            w2 + w1o, DIM, 0, 0,
            X, nullptr, DIM, 0, 0, b2 + d * DIM,
            MLPDIM, 1, 1.f, 2);
    }
}

// round 13
// speedup vs baseline: 1.9658x; 1.0438x over previous
#include <cuda_runtime.h>
#include <cuda_bf16.h>
#include <math.h>
#include <stdint.h>

#define BATCH 8
#define SEQ 512
#define DIM 768
#define NHEAD 12
#define DH 64
#define INNER 768
#define MLPDIM 3072
#define DEPTH 4
#define ROWS (BATCH * SEQ)
#define LSCALE 0.1f
#define EPS 1e-5f
#define ATT_SCALE 0.125f
#define SSQ (SEQ * SEQ)
#define QKVN (3 * INNER)          // 2304

typedef __nv_bfloat16 bf16;

// ---------------- scratch (device globals) ----------------
__device__ bf16 g_h   [ROWS * DIM];
__device__ bf16 g_qkv [ROWS * QKVN];                 // q | k | v
__device__ bf16 g_db  [BATCH * NHEAD * SSQ];         // bf16 logits
__device__ bf16 g_at  [BATCH * NHEAD * SSQ];         // post-softmax attn
__device__ bf16 g_o   [ROWS * INNER];
__device__ bf16 g_m   [ROWS * MLPDIM];
// packed / cast weights ([k][n] layout)
__device__ bf16 g_wqkv[DEPTH * DIM * QKVN];
__device__ bf16 g_wo  [DEPTH * INNER * DIM];
__device__ bf16 g_w1  [DEPTH * DIM * MLPDIM];
__device__ bf16 g_w2  [DEPTH * MLPDIM * DIM];

__device__ __forceinline__ float gelu_tanh(float x) {
    float x3 = x * x * x;
    return 0.5f * x * (1.0f + tanhf(0.7978845608028654f * (x + 0.044715f * x3)));
}

__device__ __forceinline__ void cp16(unsigned s, const void* g) {
    asm volatile("cp.async.cg.shared.global [%0], [%1], 16;\n" :: "r"(s), "l"(g));
}
__device__ __forceinline__ void cp_commit() {
    asm volatile("cp.async.commit_group;\n");
}
template<int N> __device__ __forceinline__ void cp_wait() {
    asm volatile("cp.async.wait_group %0;\n" :: "n"(N));
}
__device__ __forceinline__ void ldsm4(unsigned& r0, unsigned& r1, unsigned& r2,
                                      unsigned& r3, unsigned addr) {
    asm volatile("ldmatrix.sync.aligned.m8n8.x4.shared.b16 {%0,%1,%2,%3}, [%4];\n"
                 : "=r"(r0), "=r"(r1), "=r"(r2), "=r"(r3) : "r"(addr));
}
__device__ __forceinline__ void ldsm4t(unsigned& r0, unsigned& r1, unsigned& r2,
                                       unsigned& r3, unsigned addr) {
    asm volatile("ldmatrix.sync.aligned.m8n8.x4.trans.shared.b16 {%0,%1,%2,%3}, [%4];\n"
                 : "=r"(r0), "=r"(r1), "=r"(r2), "=r"(r3) : "r"(addr));
}
#define MMA16(d, a, b0, b1) \
    asm volatile("mma.sync.aligned.m16n8k16.row.col.f32.bf16.bf16.f32 " \
                 "{%0,%1,%2,%3},{%4,%5,%6,%7},{%8,%9},{%0,%1,%2,%3};\n" \
                 : "+f"(d[0]), "+f"(d[1]), "+f"(d[2]), "+f"(d[3])       \
                 : "r"(a[0]), "r"(a[1]), "r"(a[2]), "r"(a[3]), "r"(b0), "r"(b1))

// ---------------- cast f32 -> bf16 with column offset (weight packing) ----
__global__ __launch_bounds__(256) void wcast_pad(const float* __restrict__ in,
                                                 bf16* __restrict__ out,
                                                 int rows, int nin, int nout, int col0) {
    int i = blockIdx.x * 256 + threadIdx.x;
    int tot = rows * (nin >> 2);
    if (i < tot) {
        int r = i / (nin >> 2), c4 = i % (nin >> 2);
        float4 v = *(const float4*)(in + (size_t)r * nin + c4 * 4);
        __nv_bfloat162 p0, p1;
        p0.x = __float2bfloat16(v.x); p0.y = __float2bfloat16(v.y);
        p1.x = __float2bfloat16(v.z); p1.y = __float2bfloat16(v.w);
        __nv_bfloat162* op = (__nv_bfloat162*)(out + (size_t)r * nout + col0 + c4 * 4);
        op[0] = p0; op[1] = p1;
    }
}

// ---------------- LayerNorm -> bf16 (warp per row, 8 rows/block) ----------
__global__ __launch_bounds__(256) void ln_cast(const float* __restrict__ x,
                                               const float* __restrict__ scale,
                                               bf16* __restrict__ out) {
    int warp = threadIdx.x >> 5, lane = threadIdx.x & 31;
    int row = blockIdx.x * 8 + warp;
    const float* xr = x + (size_t)row * DIM;

    float4 v[6];
    float s = 0.f, s2 = 0.f;
    #pragma unroll
    for (int it = 0; it < 6; it++) {
        v[it] = *(const float4*)(xr + it * 128 + lane * 4);
        s  += v[it].x + v[it].y + v[it].z + v[it].w;
        s2 += v[it].x * v[it].x + v[it].y * v[it].y
            + v[it].z * v[it].z + v[it].w * v[it].w;
    }
    #pragma unroll
    for (int off = 16; off > 0; off >>= 1) {
        s  += __shfl_xor_sync(0xffffffffu, s, off);
        s2 += __shfl_xor_sync(0xffffffffu, s2, off);
    }
    float mu = s * (1.0f / DIM);
    float var = s2 * (1.0f / DIM) - mu * mu;
    float rstd = rsqrtf(var + EPS);

    bf16* outr = out + (size_t)row * DIM;
    #pragma unroll
    for (int it = 0; it < 6; it++) {
        int c = it * 128 + lane * 4;
        float4 sc = *(const float4*)(scale + c);
        __nv_bfloat162 p0, p1;
        p0.x = __float2bfloat16((v[it].x - mu) * rstd * sc.x);
        p0.y = __float2bfloat16((v[it].y - mu) * rstd * sc.y);
        p1.x = __float2bfloat16((v[it].z - mu) * rstd * sc.z);
        p1.y = __float2bfloat16((v[it].w - mu) * rstd * sc.w);
        *(__nv_bfloat162*)(outr + c)     = p0;
        *(__nv_bfloat162*)(outr + c + 2) = p1;
    }
}

// ---------------- fused mix_pre -> softmax -> mix_post (single smem buf) ---
__global__ __launch_bounds__(384) void attn_mix_softmax(
    const bf16* __restrict__ dots, const float* __restrict__ mp,
    const float* __restrict__ mq, bf16* __restrict__ at)
{
    __shared__ float S[NHEAD][SEQ];   // reused: raw dots, then softmaxed rows
    int tid = threadIdx.x, lane = tid & 31, g = tid >> 5;
    int b = blockIdx.x >> 9, i = blockIdx.x & 511;
    const bf16* base = dots + ((size_t)(b * NHEAD) * SEQ + i) * SEQ;

    #pragma unroll
    for (int it = 0; it < 2; it++) {
        int idx = tid + it * 384;                 // 0..767
        int h = idx >> 6, q = idx & 63;
        uint4 raw = *(const uint4*)(base + (size_t)h * SSQ + q * 8);
        const __nv_bfloat162* pp = (const __nv_bfloat162*)&raw;
        #pragma unroll
        for (int p = 0; p < 4; p++) {
            float2 f = __bfloat1622float2(pp[p]);
            S[h][q * 8 + 2 * p]     = f.x;
            S[h][q * 8 + 2 * p + 1] = f.y;
        }
    }
    __syncthreads();

    // mix_pre (reads S for all h) -> registers
    float mcol[NHEAD];
    #pragma unroll
    for (int h = 0; h < NHEAD; h++) mcol[h] = __ldg(&mp[h * NHEAD + g]);
    float v[16];
    float mx = -1e30f;
    #pragma unroll
    for (int k = 0; k < 16; k++) {
        int j = lane + k * 32;
        float a = 0.f;
        #pragma unroll
        for (int h = 0; h < NHEAD; h++) a += S[h][j] * mcol[h];
        v[k] = a; mx = fmaxf(mx, a);
    }
    #pragma unroll
    for (int off = 16; off > 0; off >>= 1)
        mx = fmaxf(mx, __shfl_xor_sync(0xffffffffu, mx, off));
    float s = 0.f;
    #pragma unroll
    for (int k = 0; k < 16; k++) { v[k] = __expf(v[k] - mx); s += v[k]; }
    #pragma unroll
    for (int off = 16; off > 0; off >>= 1)
        s += __shfl_xor_sync(0xffffffffu, s, off);
    float inv = 1.0f / s;

    // all mix1 reads of S are done -> safe to overwrite after barrier
    __syncthreads();
    #pragma unroll
    for (int k = 0; k < 16; k++) S[g][lane + k * 32] = v[k] * inv;
    __syncthreads();

    // mix_post
    float qcol[NHEAD];
    #pragma unroll
    for (int h = 0; h < NHEAD; h++) qcol[h] = __ldg(&mq[h * NHEAD + g]);
    size_t ob = ((size_t)((b * NHEAD + g) * SEQ) + i) * SEQ;
    #pragma unroll
    for (int k = 0; k < 16; k++) {
        int j = lane + k * 32;
        float a = 0.f;
        #pragma unroll
        for (int h = 0; h < NHEAD; h++) a += S[h][j] * qcol[h];
        at[ob + j] = __float2bfloat16(a);
    }
}

// ---------------- single-bf16 tensor-core GEMM ----------------
// A[m][k] bf16. B: TB=0 -> [n][k]; TB=1 -> [k][n] (ldmatrix.trans).
// epi: 2 X += (v+bias)*LS (f32)   4 gelu(v+bias)->bf16   5 bf16 store (alpha)
template<int BN, int WARPS_M, int WARPS_N, int TB>
__global__ __launch_bounds__(256, 2) void tgemm1(
    const bf16* __restrict__ Ap, int lda, long sAb, long sAh,
    const bf16* __restrict__ Bp, int ldb, long sBb, long sBh,
    float* __restrict__ Cf, bf16* __restrict__ Cb,
    int ldc, long sCb, long sCh, const float* __restrict__ bias,
    int K, int nH, float alpha, int epi)
{
    constexpr int BM = 128, BK = 64, STAGES = 3;
    constexpr int RB_A = 144;
    constexpr int RB_B = TB ? (BN * 2 + 16) : 144;
    constexpr unsigned OFF_B = BM * RB_A;
    constexpr unsigned B_BYTES = TB ? (BK * RB_B) : (BN * RB_B);
    constexpr unsigned STAGE = OFF_B + B_BYTES;
    constexpr int WM = BM / WARPS_M, WN = BN / WARPS_N;
    constexpr int MF = WM / 16, NF = WN / 8, NF2 = NF / 2;
    constexpr int TOT_A = BM * 8;
    constexpr int TOT_B = TB ? (BK * (BN / 8)) : (BN * 8);

    extern __shared__ __align__(16) char ds[];
    unsigned sb0 = (unsigned)__cvta_generic_to_shared(ds);

    int tid = threadIdx.x, lane = tid & 31, warp = tid >> 5;
    int wm = warp / WARPS_N, wn = warp % WARPS_N;
    int bz = blockIdx.z / nH, hz = blockIdx.z % nH;
    int row0 = blockIdx.y * BM, n0 = blockIdx.x * BN;

    const bf16* Ah = Ap + (size_t)bz * sAb + (size_t)hz * sAh + (size_t)row0 * lda;
    const bf16* Bh = Bp + (size_t)bz * sBb + (size_t)hz * sBh
                        + (TB ? (size_t)n0 : (size_t)n0 * ldb);

    const int KT = K / BK;

    auto load_stage = [&](int t) {
        unsigned sbm = sb0 + (unsigned)(t % STAGES) * STAGE;
        int k0 = t * BK;
        #pragma unroll
        for (int c = tid; c < TOT_A + TOT_B; c += 256) {
            if (c < TOT_A) {
                int r = c >> 3, q = c & 7;
                cp16(sbm + (unsigned)(r * RB_A + q * 16),
                     Ah + (size_t)r * lda + k0 + q * 8);
            } else if (TB) {
                int cc = c - TOT_A;
                int r = cc / (BN / 8), q = cc % (BN / 8);
                cp16(sbm + OFF_B + (unsigned)(r * RB_B + q * 16),
                     Bh + (size_t)(k0 + r) * ldb + q * 8);
            } else {
                int cc = c - TOT_A;
                int r = cc >> 3, q = cc & 7;
                cp16(sbm + OFF_B + (unsigned)(r * RB_B + q * 16),
                     Bh + (size_t)r * ldb + k0 + q * 8);
            }
        }
    };

    float acc[MF][NF][4] = {};

    #pragma unroll
    for (int s = 0; s < STAGES - 1; s++)
        if (s < KT) { load_stage(s); cp_commit(); }

    int arow = lane & 15;
    int acol = (lane >> 4) << 4;
    int nrow = (lane & 7) | ((lane & 16) >> 1);
    int ncol = (lane & 8) ? 16 : 0;
    int krow = lane & 15;
    int noff = (lane & 16) ? 16 : 0;

    for (int t = 0; t < KT; t++) {
        if (t + 1 < KT) cp_wait<1>(); else cp_wait<0>();
        __syncthreads();
        if (t + STAGES - 1 < KT) { load_stage(t + STAGES - 1); cp_commit(); }

        unsigned sbm = sb0 + (unsigned)(t % STAGES) * STAGE;
        #pragma unroll
        for (int kk = 0; kk < BK / 16; kk++) {
            unsigned ah[MF][4], bh[NF2][4];
            #pragma unroll
            for (int mi = 0; mi < MF; mi++) {
                unsigned base = sbm + (unsigned)((wm * WM + mi * 16 + arow) * RB_A + kk * 32 + acol);
                ldsm4(ah[mi][0], ah[mi][1], ah[mi][2], ah[mi][3], base);
            }
            #pragma unroll
            for (int j = 0; j < NF2; j++) {
                if (TB) {
                    unsigned base = sbm + OFF_B
                        + (unsigned)((kk * 16 + krow) * RB_B + (wn * WN + j * 16) * 2 + noff);
                    ldsm4t(bh[j][0], bh[j][1], bh[j][2], bh[j][3], base);
                } else {
                    unsigned base = sbm + OFF_B
                        + (unsigned)((wn * WN + j * 16 + nrow) * RB_B + kk * 32 + ncol);
                    ldsm4(bh[j][0], bh[j][1], bh[j][2], bh[j][3], base);
                }
            }
            #pragma unroll
            for (int mi = 0; mi < MF; mi++)
                #pragma unroll
                for (int ni = 0; ni < NF; ni++) {
                    int j = ni >> 1, o = (ni & 1) * 2;
                    MMA16(acc[mi][ni], ah[mi], bh[j][o], bh[j][o + 1]);
                }
        }
    }

    // ---- epilogue ----
    float* Cfb = Cf ? Cf + (size_t)bz * sCb + (size_t)hz * sCh : nullptr;
    bf16* Cbb = Cb ? Cb + (size_t)bz * sCb + (size_t)hz * sCh : nullptr;

    #pragma unroll
    for (int mi = 0; mi < MF; mi++) {
        #pragma unroll
        for (int ni = 0; ni < NF; ni++) {
            int r0 = row0 + wm * WM + mi * 16 + (lane >> 2);
            int cn = n0 + wn * WN + ni * 8 + 2 * (lane & 3);
            #pragma unroll
            for (int half = 0; half < 2; half++) {
                int r = r0 + half * 8;
                float v0 = acc[mi][ni][half * 2 + 0] * alpha;
                float v1 = acc[mi][ni][half * 2 + 1] * alpha;
                size_t off = (size_t)r * ldc + cn;
                if (epi == 2) {
                    float2 old = *(float2*)(Cfb + off);
                    old.x += (v0 + bias[cn]) * LSCALE;
                    old.y += (v1 + bias[cn + 1]) * LSCALE;
                    *(float2*)(Cfb + off) = old;
                } else if (epi == 4) {
                    __nv_bfloat162 p;
                    p.x = __float2bfloat16(gelu_tanh(v0 + bias[cn]));
                    p.y = __float2bfloat16(gelu_tanh(v1 + bias[cn + 1]));
                    *(__nv_bfloat162*)(Cbb + off) = p;
                } else {   // 5
                    __nv_bfloat162 p;
                    p.x = __float2bfloat16(v0);
                    p.y = __float2bfloat16(v1);
                    *(__nv_bfloat162*)(Cbb + off) = p;
                }
            }
        }
    }
}

// ---------------- launch ----------------
extern "C" void kernel_launch(void* const* d_in, const int* in_sizes, int n_in,
                              void* d_out, int out_size) {
    const float* x_in     = (const float*)d_in[0];
    const float* ln1      = (const float*)d_in[1];
    const float* Wq       = (const float*)d_in[2];
    const float* Wkv      = (const float*)d_in[3];
    const float* mix_pre  = (const float*)d_in[4];
    const float* mix_post = (const float*)d_in[5];
    const float* Wo       = (const float*)d_in[6];
    const float* bo       = (const float*)d_in[7];
    const float* ln2      = (const float*)d_in[8];
    const float* W1       = (const float*)d_in[9];
    const float* b1       = (const float*)d_in[10];
    const float* W2       = (const float*)d_in[11];
    const float* b2       = (const float*)d_in[12];

    float* X = (float*)d_out;

    bf16 *h, *qkv, *db, *at, *o, *m;
    bf16 *wqkv, *wo, *w1, *w2;
    cudaGetSymbolAddress((void**)&h,   g_h);
    cudaGetSymbolAddress((void**)&qkv, g_qkv);
    cudaGetSymbolAddress((void**)&db,  g_db);
    cudaGetSymbolAddress((void**)&at,  g_at);
    cudaGetSymbolAddress((void**)&o,   g_o);
    cudaGetSymbolAddress((void**)&m,   g_m);
    cudaGetSymbolAddress((void**)&wqkv, g_wqkv);
    cudaGetSymbolAddress((void**)&wo,   g_wo);
    cudaGetSymbolAddress((void**)&w1,   g_w1);
    cudaGetSymbolAddress((void**)&w2,   g_w2);

    const int SM_T1_128 = 3 * (128 * 144 + 64 * (128 * 2 + 16));  // 107520
    const int SM_T0_128 = 3 * (128 * 144 + 128 * 144);            // 110592
    const int SM_T1_64  = 3 * (128 * 144 + 64 * (64 * 2 + 16));   // 82944
    cudaFuncSetAttribute((const void*)tgemm1<128, 2, 4, 1>,
                         cudaFuncAttributeMaxDynamicSharedMemorySize, SM_T1_128);
    cudaFuncSetAttribute((const void*)tgemm1<128, 2, 4, 0>,
                         cudaFuncAttributeMaxDynamicSharedMemorySize, SM_T0_128);
    cudaFuncSetAttribute((const void*)tgemm1<64, 4, 2, 1>,
                         cudaFuncAttributeMaxDynamicSharedMemorySize, SM_T1_64);

    cudaMemcpyAsync(X, x_in, (size_t)ROWS * DIM * sizeof(float),
                    cudaMemcpyDeviceToDevice);

    // ---- weight cast + pack (wq|wkv -> wqkv), plain casts for the rest ----
    {
        int tot;
        tot = DEPTH * DIM * (INNER / 4);            // Wq -> cols [0,768)
        wcast_pad<<<(tot + 255) / 256, 256>>>(Wq, wqkv, DEPTH * DIM, INNER, QKVN, 0);
        tot = DEPTH * DIM * (2 * INNER / 4);        // Wkv -> cols [768,2304)
        wcast_pad<<<(tot + 255) / 256, 256>>>(Wkv, wqkv, DEPTH * DIM, 2 * INNER, QKVN, INNER);
        tot = DEPTH * INNER * (DIM / 4);
        wcast_pad<<<(tot + 255) / 256, 256>>>(Wo, wo, DEPTH * INNER, DIM, DIM, 0);
        tot = DEPTH * DIM * (MLPDIM / 4);
        wcast_pad<<<(tot + 255) / 256, 256>>>(W1, w1, DEPTH * DIM, MLPDIM, MLPDIM, 0);
        tot = DEPTH * MLPDIM * (DIM / 4);
        wcast_pad<<<(tot + 255) / 256, 256>>>(W2, w2, DEPTH * MLPDIM, DIM, DIM, 0);
    }

    for (int d = 0; d < DEPTH; d++) {
        size_t wqkvo = (size_t)d * DIM * QKVN;
        size_t woo   = (size_t)d * INNER * DIM;
        size_t w1o   = (size_t)d * DIM * MLPDIM;

        // ---- attention half ----
        ln_cast<<<ROWS / 8, 256>>>(X, ln1 + d * DIM, h);

        // qkv = h @ [Wq|Wk|Wv]   (one GEMM, N=2304)
        tgemm1<128, 2, 4, 1><<<dim3(QKVN / 128, ROWS / 128, 1), 256, SM_T1_128>>>(
            h, DIM, 0, 0,
            wqkv + wqkvo, QKVN, 0, 0,
            nullptr, qkv, QKVN, 0, 0, nullptr,
            DIM, 1, 1.f, 5);

        // dots(bf16) = scale * q @ k^T per (b,h)
        tgemm1<128, 2, 4, 0><<<dim3(SEQ / 128, SEQ / 128, BATCH * NHEAD), 256, SM_T0_128>>>(
            qkv, QKVN, (long)SEQ * QKVN, DH,
            qkv + INNER, QKVN, (long)SEQ * QKVN, DH,
            nullptr, db, SEQ, (long)NHEAD * SSQ, (long)SSQ, nullptr,
            DH, NHEAD, ATT_SCALE, 5);

        attn_mix_softmax<<<BATCH * SEQ, 384>>>(db, mix_pre + d * NHEAD * NHEAD,
                                               mix_post + d * NHEAD * NHEAD, at);

        // o = attn @ v   (v natural [j][d] in qkv -> trans path)
        tgemm1<64, 4, 2, 1><<<dim3(1, SEQ / 128, BATCH * NHEAD), 256, SM_T1_64>>>(
            at, SEQ, (long)NHEAD * SSQ, (long)SSQ,
            qkv + 2 * INNER, QKVN, (long)SEQ * QKVN, (long)DH,
            nullptr, o, INNER, (long)SEQ * INNER, (long)DH, nullptr,
            SEQ, NHEAD, 1.f, 5);

        // X += (o @ Wo + bo) * LS
        tgemm1<64, 4, 2, 1><<<dim3(DIM / 64, ROWS / 128, 1), 256, SM_T1_64>>>(
            o, INNER, 0, 0,
            wo + woo, DIM, 0, 0,
            X, nullptr, DIM, 0, 0, bo + d * DIM,
            INNER, 1, 1.f, 2);

        // ---- MLP half ----
        ln_cast<<<ROWS / 8, 256>>>(X, ln2 + d * DIM, h);

        tgemm1<128, 2, 4, 1><<<dim3(MLPDIM / 128, ROWS / 128, 1), 256, SM_T1_128>>>(
            h, DIM, 0, 0,
            w1 + w1o, MLPDIM, 0, 0,
            nullptr, m, MLPDIM, 0, 0, b1 + d * MLPDIM,
            DIM, 1, 1.f, 4);

        tgemm1<64, 4, 2, 1><<<dim3(DIM / 64, ROWS / 128, 1), 256, SM_T1_64>>>(
            m, MLPDIM, 0, 0,
            w2 + w1o, DIM, 0, 0,
            X, nullptr, DIM, 0, 0, b2 + d * DIM,
            MLPDIM, 1, 1.f, 2);
    }
}

// round 14
// speedup vs baseline: 2.0253x; 1.0302x over previous
#include <cuda_runtime.h>
#include <cuda_bf16.h>
#include <math.h>
#include <stdint.h>

#define BATCH 8
#define SEQ 512
#define DIM 768
#define NHEAD 12
#define DH 64
#define INNER 768
#define MLPDIM 3072
#define DEPTH 4
#define ROWS (BATCH * SEQ)
#define LSCALE 0.1f
#define EPS 1e-5f
#define ATT_SCALE 0.125f
#define SSQ (SEQ * SEQ)
#define QKVN (3 * INNER)          // 2304

typedef __nv_bfloat16 bf16;

// ---------------- scratch (device globals) ----------------
__device__ bf16 g_h   [ROWS * DIM];
__device__ bf16 g_qkv [ROWS * QKVN];                 // q | k | v
__device__ bf16 g_db  [BATCH * NHEAD * SSQ];         // bf16 logits
__device__ bf16 g_at  [BATCH * NHEAD * SSQ];         // post-softmax attn
__device__ bf16 g_o   [ROWS * INNER];
__device__ bf16 g_m   [ROWS * MLPDIM];
// packed / cast weights ([k][n] layout)
__device__ bf16 g_wqkv[DEPTH * DIM * QKVN];
__device__ bf16 g_wo  [DEPTH * INNER * DIM];
__device__ bf16 g_w1  [DEPTH * DIM * MLPDIM];
__device__ bf16 g_w2  [DEPTH * MLPDIM * DIM];

__device__ __forceinline__ float gelu_tanh(float x) {
    float x3 = x * x * x;
    return 0.5f * x * (1.0f + tanhf(0.7978845608028654f * (x + 0.044715f * x3)));
}

__device__ __forceinline__ void cp16(unsigned s, const void* g) {
    asm volatile("cp.async.cg.shared.global [%0], [%1], 16;\n" :: "r"(s), "l"(g));
}
__device__ __forceinline__ void cp_commit() {
    asm volatile("cp.async.commit_group;\n");
}
template<int N> __device__ __forceinline__ void cp_wait() {
    asm volatile("cp.async.wait_group %0;\n" :: "n"(N));
}
__device__ __forceinline__ void ldsm4(unsigned& r0, unsigned& r1, unsigned& r2,
                                      unsigned& r3, unsigned addr) {
    asm volatile("ldmatrix.sync.aligned.m8n8.x4.shared.b16 {%0,%1,%2,%3}, [%4];\n"
                 : "=r"(r0), "=r"(r1), "=r"(r2), "=r"(r3) : "r"(addr));
}
__device__ __forceinline__ void ldsm4t(unsigned& r0, unsigned& r1, unsigned& r2,
                                       unsigned& r3, unsigned addr) {
    asm volatile("ldmatrix.sync.aligned.m8n8.x4.trans.shared.b16 {%0,%1,%2,%3}, [%4];\n"
                 : "=r"(r0), "=r"(r1), "=r"(r2), "=r"(r3) : "r"(addr));
}
#define MMA16(d, a, b0, b1) \
    asm volatile("mma.sync.aligned.m16n8k16.row.col.f32.bf16.bf16.f32 " \
                 "{%0,%1,%2,%3},{%4,%5,%6,%7},{%8,%9},{%0,%1,%2,%3};\n" \
                 : "+f"(d[0]), "+f"(d[1]), "+f"(d[2]), "+f"(d[3])       \
                 : "r"(a[0]), "r"(a[1]), "r"(a[2]), "r"(a[3]), "r"(b0), "r"(b1))

// ---------------- merged weight cast (all 5 tensors, one launch) ----------
struct CastArgs {
    const float* in[5];
    bf16* out[5];
    int nin4[5];     // nin/4
    int nout[5];
    int col0[5];
    long start[6];   // prefix over float4 counts
};

__global__ __launch_bounds__(256) void wcast_all(CastArgs a) {
    long i = (long)blockIdx.x * 256 + threadIdx.x;
    if (i >= a.start[5]) return;
    int s = 0;
    #pragma unroll
    for (int k = 1; k < 5; k++) if (i >= a.start[k]) s = k;
    long j = i - a.start[s];
    int nin4 = a.nin4[s];
    int r = (int)(j / nin4), c4 = (int)(j % nin4);
    float4 v = *(const float4*)(a.in[s] + ((size_t)r * nin4 + c4) * 4);
    __nv_bfloat162 p0, p1;
    p0.x = __float2bfloat16(v.x); p0.y = __float2bfloat16(v.y);
    p1.x = __float2bfloat16(v.z); p1.y = __float2bfloat16(v.w);
    __nv_bfloat162* op = (__nv_bfloat162*)(a.out[s] + (size_t)r * a.nout[s]
                                           + a.col0[s] + c4 * 4);
    op[0] = p0; op[1] = p1;
}

// ---------------- LayerNorm -> bf16 (warp per row, 8 rows/block) ----------
__global__ __launch_bounds__(256) void ln_cast(const float* __restrict__ x,
                                               const float* __restrict__ scale,
                                               bf16* __restrict__ out) {
    int warp = threadIdx.x >> 5, lane = threadIdx.x & 31;
    int row = blockIdx.x * 8 + warp;
    const float* xr = x + (size_t)row * DIM;

    float4 v[6];
    float s = 0.f, s2 = 0.f;
    #pragma unroll
    for (int it = 0; it < 6; it++) {
        v[it] = *(const float4*)(xr + it * 128 + lane * 4);
        s  += v[it].x + v[it].y + v[it].z + v[it].w;
        s2 += v[it].x * v[it].x + v[it].y * v[it].y
            + v[it].z * v[it].z + v[it].w * v[it].w;
    }
    #pragma unroll
    for (int off = 16; off > 0; off >>= 1) {
        s  += __shfl_xor_sync(0xffffffffu, s, off);
        s2 += __shfl_xor_sync(0xffffffffu, s2, off);
    }
    float mu = s * (1.0f / DIM);
    float var = s2 * (1.0f / DIM) - mu * mu;
    float rstd = rsqrtf(var + EPS);

    bf16* outr = out + (size_t)row * DIM;
    #pragma unroll
    for (int it = 0; it < 6; it++) {
        int c = it * 128 + lane * 4;
        float4 sc = *(const float4*)(scale + c);
        __nv_bfloat162 p0, p1;
        p0.x = __float2bfloat16((v[it].x - mu) * rstd * sc.x);
        p0.y = __float2bfloat16((v[it].y - mu) * rstd * sc.y);
        p1.x = __float2bfloat16((v[it].z - mu) * rstd * sc.z);
        p1.y = __float2bfloat16((v[it].w - mu) * rstd * sc.w);
        *(__nv_bfloat162*)(outr + c)     = p0;
        *(__nv_bfloat162*)(outr + c + 2) = p1;
    }
}

// ---------------- fused mix_pre -> softmax -> mix_post (single smem buf) ---
__global__ __launch_bounds__(384) void attn_mix_softmax(
    const bf16* __restrict__ dots, const float* __restrict__ mp,
    const float* __restrict__ mq, bf16* __restrict__ at)
{
    __shared__ float S[NHEAD][SEQ];
    int tid = threadIdx.x, lane = tid & 31, g = tid >> 5;
    int b = blockIdx.x >> 9, i = blockIdx.x & 511;
    const bf16* base = dots + ((size_t)(b * NHEAD) * SEQ + i) * SEQ;

    #pragma unroll
    for (int it = 0; it < 2; it++) {
        int idx = tid + it * 384;
        int h = idx >> 6, q = idx & 63;
        uint4 raw = *(const uint4*)(base + (size_t)h * SSQ + q * 8);
        const __nv_bfloat162* pp = (const __nv_bfloat162*)&raw;
        #pragma unroll
        for (int p = 0; p < 4; p++) {
            float2 f = __bfloat1622float2(pp[p]);
            S[h][q * 8 + 2 * p]     = f.x;
            S[h][q * 8 + 2 * p + 1] = f.y;
        }
    }
    __syncthreads();

    float mcol[NHEAD];
    #pragma unroll
    for (int h = 0; h < NHEAD; h++) mcol[h] = __ldg(&mp[h * NHEAD + g]);
    float v[16];
    float mx = -1e30f;
    #pragma unroll
    for (int k = 0; k < 16; k++) {
        int j = lane + k * 32;
        float a = 0.f;
        #pragma unroll
        for (int h = 0; h < NHEAD; h++) a += S[h][j] * mcol[h];
        v[k] = a; mx = fmaxf(mx, a);
    }
    #pragma unroll
    for (int off = 16; off > 0; off >>= 1)
        mx = fmaxf(mx, __shfl_xor_sync(0xffffffffu, mx, off));
    float s = 0.f;
    #pragma unroll
    for (int k = 0; k < 16; k++) { v[k] = __expf(v[k] - mx); s += v[k]; }
    #pragma unroll
    for (int off = 16; off > 0; off >>= 1)
        s += __shfl_xor_sync(0xffffffffu, s, off);
    float inv = 1.0f / s;

    __syncthreads();
    #pragma unroll
    for (int k = 0; k < 16; k++) S[g][lane + k * 32] = v[k] * inv;
    __syncthreads();

    float qcol[NHEAD];
    #pragma unroll
    for (int h = 0; h < NHEAD; h++) qcol[h] = __ldg(&mq[h * NHEAD + g]);
    size_t ob = ((size_t)((b * NHEAD + g) * SEQ) + i) * SEQ;
    #pragma unroll
    for (int k = 0; k < 16; k++) {
        int j = lane + k * 32;
        float a = 0.f;
        #pragma unroll
        for (int h = 0; h < NHEAD; h++) a += S[h][j] * qcol[h];
        at[ob + j] = __float2bfloat16(a);
    }
}

// ---------------- single-bf16 tensor-core GEMM ----------------
// A[m][k] bf16. B: TB=0 -> [n][k]; TB=1 -> [k][n] (ldmatrix.trans).
// epi: 2 Cf = Rf + (v+bias)*LS (f32, Rf may alias Cf)
//      4 gelu(v+bias)->bf16     5 bf16 store (alpha)
template<int BN, int WARPS_M, int WARPS_N, int TB, int STG>
__global__ __launch_bounds__(256, 2) void tgemm1(
    const bf16* __restrict__ Ap, int lda, long sAb, long sAh,
    const bf16* __restrict__ Bp, int ldb, long sBb, long sBh,
    float* __restrict__ Cf, const float* __restrict__ Rf, bf16* __restrict__ Cb,
    int ldc, long sCb, long sCh, const float* __restrict__ bias,
    int K, int nH, float alpha, int epi)
{
    constexpr int BM = 128, BK = 64;
    constexpr int RB_A = 144;
    constexpr int RB_B = TB ? (BN * 2 + 16) : 144;
    constexpr unsigned OFF_B = BM * RB_A;
    constexpr unsigned B_BYTES = TB ? (BK * RB_B) : (BN * RB_B);
    constexpr unsigned STAGE = OFF_B + B_BYTES;
    constexpr int WM = BM / WARPS_M, WN = BN / WARPS_N;
    constexpr int MF = WM / 16, NF = WN / 8, NF2 = NF / 2;
    constexpr int TOT_A = BM * 8;
    constexpr int TOT_B = TB ? (BK * (BN / 8)) : (BN * 8);

    extern __shared__ __align__(16) char ds[];
    unsigned sb0 = (unsigned)__cvta_generic_to_shared(ds);

    int tid = threadIdx.x, lane = tid & 31, warp = tid >> 5;
    int wm = warp / WARPS_N, wn = warp % WARPS_N;
    int bz = blockIdx.z / nH, hz = blockIdx.z % nH;
    int row0 = blockIdx.y * BM, n0 = blockIdx.x * BN;

    const bf16* Ah = Ap + (size_t)bz * sAb + (size_t)hz * sAh + (size_t)row0 * lda;
    const bf16* Bh = Bp + (size_t)bz * sBb + (size_t)hz * sBh
                        + (TB ? (size_t)n0 : (size_t)n0 * ldb);

    const int KT = K / BK;

    auto load_stage = [&](int t) {
        unsigned sbm = sb0 + (unsigned)(t % STG) * STAGE;
        int k0 = t * BK;
        #pragma unroll
        for (int c = tid; c < TOT_A + TOT_B; c += 256) {
            if (c < TOT_A) {
                int r = c >> 3, q = c & 7;
                cp16(sbm + (unsigned)(r * RB_A + q * 16),
                     Ah + (size_t)r * lda + k0 + q * 8);
            } else if (TB) {
                int cc = c - TOT_A;
                int r = cc / (BN / 8), q = cc % (BN / 8);
                cp16(sbm + OFF_B + (unsigned)(r * RB_B + q * 16),
                     Bh + (size_t)(k0 + r) * ldb + q * 8);
            } else {
                int cc = c - TOT_A;
                int r = cc >> 3, q = cc & 7;
                cp16(sbm + OFF_B + (unsigned)(r * RB_B + q * 16),
                     Bh + (size_t)r * ldb + k0 + q * 8);
            }
        }
    };

    float acc[MF][NF][4] = {};

    #pragma unroll
    for (int s = 0; s < STG - 1; s++)
        if (s < KT) { load_stage(s); cp_commit(); }

    int arow = lane & 15;
    int acol = (lane >> 4) << 4;
    int nrow = (lane & 7) | ((lane & 16) >> 1);
    int ncol = (lane & 8) ? 16 : 0;
    int krow = lane & 15;
    int noff = (lane & 16) ? 16 : 0;

    for (int t = 0; t < KT; t++) {
        int rem = KT - 1 - t;      // future stages still to load
        if (rem >= STG - 2)      cp_wait<STG - 2>();
        else if (rem == 2)       cp_wait<2>();
        else if (rem == 1)       cp_wait<1>();
        else                     cp_wait<0>();
        __syncthreads();
        if (t + STG - 1 < KT) { load_stage(t + STG - 1); cp_commit(); }

        unsigned sbm = sb0 + (unsigned)(t % STG) * STAGE;
        #pragma unroll
        for (int kk = 0; kk < BK / 16; kk++) {
            unsigned ah[MF][4], bh[NF2][4];
            #pragma unroll
            for (int mi = 0; mi < MF; mi++) {
                unsigned base = sbm + (unsigned)((wm * WM + mi * 16 + arow) * RB_A + kk * 32 + acol);
                ldsm4(ah[mi][0], ah[mi][1], ah[mi][2], ah[mi][3], base);
            }
            #pragma unroll
            for (int j = 0; j < NF2; j++) {
                if (TB) {
                    unsigned base = sbm + OFF_B
                        + (unsigned)((kk * 16 + krow) * RB_B + (wn * WN + j * 16) * 2 + noff);
                    ldsm4t(bh[j][0], bh[j][1], bh[j][2], bh[j][3], base);
                } else {
                    unsigned base = sbm + OFF_B
                        + (unsigned)((wn * WN + j * 16 + nrow) * RB_B + kk * 32 + ncol);
                    ldsm4(bh[j][0], bh[j][1], bh[j][2], bh[j][3], base);
                }
            }
            #pragma unroll
            for (int mi = 0; mi < MF; mi++)
                #pragma unroll
                for (int ni = 0; ni < NF; ni++) {
                    int j = ni >> 1, o = (ni & 1) * 2;
                    MMA16(acc[mi][ni], ah[mi], bh[j][o], bh[j][o + 1]);
                }
        }
    }

    // ---- epilogue ----
    float* Cfb = Cf ? Cf + (size_t)bz * sCb + (size_t)hz * sCh : nullptr;
    const float* Rfb = Rf ? Rf + (size_t)bz * sCb + (size_t)hz * sCh : nullptr;
    bf16* Cbb = Cb ? Cb + (size_t)bz * sCb + (size_t)hz * sCh : nullptr;

    #pragma unroll
    for (int mi = 0; mi < MF; mi++) {
        #pragma unroll
        for (int ni = 0; ni < NF; ni++) {
            int r0 = row0 + wm * WM + mi * 16 + (lane >> 2);
            int cn = n0 + wn * WN + ni * 8 + 2 * (lane & 3);
            #pragma unroll
            for (int half = 0; half < 2; half++) {
                int r = r0 + half * 8;
                float v0 = acc[mi][ni][half * 2 + 0] * alpha;
                float v1 = acc[mi][ni][half * 2 + 1] * alpha;
                size_t off = (size_t)r * ldc + cn;
                if (epi == 2) {
                    float2 old = *(const float2*)(Rfb + off);
                    old.x += (v0 + bias[cn]) * LSCALE;
                    old.y += (v1 + bias[cn + 1]) * LSCALE;
                    *(float2*)(Cfb + off) = old;
                } else if (epi == 4) {
                    __nv_bfloat162 p;
                    p.x = __float2bfloat16(gelu_tanh(v0 + bias[cn]));
                    p.y = __float2bfloat16(gelu_tanh(v1 + bias[cn + 1]));
                    *(__nv_bfloat162*)(Cbb + off) = p;
                } else {   // 5
                    __nv_bfloat162 p;
                    p.x = __float2bfloat16(v0);
                    p.y = __float2bfloat16(v1);
                    *(__nv_bfloat162*)(Cbb + off) = p;
                }
            }
        }
    }
}

// ---------------- launch ----------------
extern "C" void kernel_launch(void* const* d_in, const int* in_sizes, int n_in,
                              void* d_out, int out_size) {
    const float* x_in     = (const float*)d_in[0];
    const float* ln1      = (const float*)d_in[1];
    const float* Wq       = (const float*)d_in[2];
    const float* Wkv      = (const float*)d_in[3];
    const float* mix_pre  = (const float*)d_in[4];
    const float* mix_post = (const float*)d_in[5];
    const float* Wo       = (const float*)d_in[6];
    const float* bo       = (const float*)d_in[7];
    const float* ln2      = (const float*)d_in[8];
    const float* W1       = (const float*)d_in[9];
    const float* b1       = (const float*)d_in[10];
    const float* W2       = (const float*)d_in[11];
    const float* b2       = (const float*)d_in[12];

    float* X = (float*)d_out;

    bf16 *h, *qkv, *db, *at, *o, *m;
    bf16 *wqkv, *wo, *w1, *w2;
    cudaGetSymbolAddress((void**)&h,   g_h);
    cudaGetSymbolAddress((void**)&qkv, g_qkv);
    cudaGetSymbolAddress((void**)&db,  g_db);
    cudaGetSymbolAddress((void**)&at,  g_at);
    cudaGetSymbolAddress((void**)&o,   g_o);
    cudaGetSymbolAddress((void**)&m,   g_m);
    cudaGetSymbolAddress((void**)&wqkv, g_wqkv);
    cudaGetSymbolAddress((void**)&wo,   g_wo);
    cudaGetSymbolAddress((void**)&w1,   g_w1);
    cudaGetSymbolAddress((void**)&w2,   g_w2);

    const int SM_T1_128 = 3 * (128 * 144 + 64 * (128 * 2 + 16));  // 107520
    const int SM_T0_128 = 3 * (128 * 144 + 128 * 144);            // 110592
    const int SM_T1_64  = 4 * (128 * 144 + 64 * (64 * 2 + 16));   // 110592
    cudaFuncSetAttribute((const void*)tgemm1<128, 2, 4, 1, 3>,
                         cudaFuncAttributeMaxDynamicSharedMemorySize, SM_T1_128);
    cudaFuncSetAttribute((const void*)tgemm1<128, 2, 4, 0, 3>,
                         cudaFuncAttributeMaxDynamicSharedMemorySize, SM_T0_128);
    cudaFuncSetAttribute((const void*)tgemm1<64, 4, 2, 1, 4>,
                         cudaFuncAttributeMaxDynamicSharedMemorySize, SM_T1_64);

    // ---- merged weight cast + pack (one launch) ----
    {
        CastArgs a;
        long n4[5];
        // seg 0: Wq  -> wqkv cols [0,768)
        a.in[0] = Wq;  a.out[0] = wqkv; a.nin4[0] = INNER / 4;
        a.nout[0] = QKVN; a.col0[0] = 0;
        n4[0] = (long)DEPTH * DIM * (INNER / 4);
        // seg 1: Wkv -> wqkv cols [768,2304)
        a.in[1] = Wkv; a.out[1] = wqkv; a.nin4[1] = 2 * INNER / 4;
        a.nout[1] = QKVN; a.col0[1] = INNER;
        n4[1] = (long)DEPTH * DIM * (2 * INNER / 4);
        // seg 2: Wo
        a.in[2] = Wo;  a.out[2] = wo;   a.nin4[2] = DIM / 4;
        a.nout[2] = DIM; a.col0[2] = 0;
        n4[2] = (long)DEPTH * INNER * (DIM / 4);
        // seg 3: W1
        a.in[3] = W1;  a.out[3] = w1;   a.nin4[3] = MLPDIM / 4;
        a.nout[3] = MLPDIM; a.col0[3] = 0;
        n4[3] = (long)DEPTH * DIM * (MLPDIM / 4);
        // seg 4: W2
        a.in[4] = W2;  a.out[4] = w2;   a.nin4[4] = DIM / 4;
        a.nout[4] = DIM; a.col0[4] = 0;
        n4[4] = (long)DEPTH * MLPDIM * (DIM / 4);
        a.start[0] = 0;
        for (int s = 0; s < 5; s++) a.start[s + 1] = a.start[s] + n4[s];
        long tot = a.start[5];
        wcast_all<<<(unsigned)((tot + 255) / 256), 256>>>(a);
    }

    for (int d = 0; d < DEPTH; d++) {
        size_t wqkvo = (size_t)d * DIM * QKVN;
        size_t woo   = (size_t)d * INNER * DIM;
        size_t w1o   = (size_t)d * DIM * MLPDIM;
        const float* Xsrc = (d == 0) ? x_in : X;   // residual source for attn half

        // ---- attention half ----
        ln_cast<<<ROWS / 8, 256>>>(Xsrc, ln1 + d * DIM, h);

        // qkv = h @ [Wq|Wk|Wv]
        tgemm1<128, 2, 4, 1, 3><<<dim3(QKVN / 128, ROWS / 128, 1), 256, SM_T1_128>>>(
            h, DIM, 0, 0,
            wqkv + wqkvo, QKVN, 0, 0,
            nullptr, nullptr, qkv, QKVN, 0, 0, nullptr,
            DIM, 1, 1.f, 5);

        // dots(bf16) = scale * q @ k^T per (b,h)
        tgemm1<128, 2, 4, 0, 3><<<dim3(SEQ / 128, SEQ / 128, BATCH * NHEAD), 256, SM_T0_128>>>(
            qkv, QKVN, (long)SEQ * QKVN, DH,
            qkv + INNER, QKVN, (long)SEQ * QKVN, DH,
            nullptr, nullptr, db, SEQ, (long)NHEAD * SSQ, (long)SSQ, nullptr,
            DH, NHEAD, ATT_SCALE, 5);

        attn_mix_softmax<<<BATCH * SEQ, 384>>>(db, mix_pre + d * NHEAD * NHEAD,
                                               mix_post + d * NHEAD * NHEAD, at);

        // o = attn @ v
        tgemm1<64, 4, 2, 1, 4><<<dim3(1, SEQ / 128, BATCH * NHEAD), 256, SM_T1_64>>>(
            at, SEQ, (long)NHEAD * SSQ, (long)SSQ,
            qkv + 2 * INNER, QKVN, (long)SEQ * QKVN, (long)DH,
            nullptr, nullptr, o, INNER, (long)SEQ * INNER, (long)DH, nullptr,
            SEQ, NHEAD, 1.f, 5);

        // X = Xsrc + (o @ Wo + bo) * LS   (layer 0: Xsrc = x_in, no memcpy)
        tgemm1<64, 4, 2, 1, 4><<<dim3(DIM / 64, ROWS / 128, 1), 256, SM_T1_64>>>(
            o, INNER, 0, 0,
            wo + woo, DIM, 0, 0,
            X, Xsrc, nullptr, DIM, 0, 0, bo + d * DIM,
            INNER, 1, 1.f, 2);

        // ---- MLP half ----
        ln_cast<<<ROWS / 8, 256>>>(X, ln2 + d * DIM, h);

        tgemm1<128, 2, 4, 1, 3><<<dim3(MLPDIM / 128, ROWS / 128, 1), 256, SM_T1_128>>>(
            h, DIM, 0, 0,
            w1 + w1o, MLPDIM, 0, 0,
            nullptr, nullptr, m, MLPDIM, 0, 0, b1 + d * MLPDIM,
            DIM, 1, 1.f, 4);

        tgemm1<64, 4, 2, 1, 4><<<dim3(DIM / 64, ROWS / 128, 1), 256, SM_T1_64>>>(
            m, MLPDIM, 0, 0,
            w2 + w1o, DIM, 0, 0,
            X, X, nullptr, DIM, 0, 0, b2 + d * DIM,
            MLPDIM, 1, 1.f, 2);
    }
}